// round 4
// baseline (speedup 1.0000x reference)
#include <cuda_runtime.h>
#include <cstdint>
#include <math.h>

#define NB 16
#define NN 1024
#define HH 256
#define LH 768          // H*(1+L) = 768

// ---------------- scratch (__device__ globals; no cudaMalloc allowed) ----------------
__device__ float g_hall[(size_t)NB * 4 * NN * HH];   // [b][c][n][h]
__device__ float g_hcat[(size_t)NB * NN * LH];       // [b*n][768]  (h0|h1|h2)
__device__ float g_t0[(size_t)NB * NN * HH];
__device__ float g_t1[(size_t)NB * NN * HH];
__device__ float g_t2[(size_t)NB * NN * HH];
__device__ float g_hp[(size_t)NB * NN * HH];         // h_prime
__device__ float g_ht[(size_t)NB * NN * HH];         // after w1
__device__ float g_m1[(size_t)NB * NN * HH];         // after mlp1
__device__ float g_dis[NB * NN];                     // (rowsum(adj)+1)^-0.5
__device__ float g_rsinv[NB * NN];                   // 1/rowsum(adj)
__device__ float g_u[NB * NN];
__device__ float g_v[NB * NN];
__device__ float g_r[NB * NN];
__device__ float g_c[NB * NN];

// ---------------- helpers ----------------
__device__ __forceinline__ float lky(float x) { return x > 0.0f ? x : 0.01f * x; }

__device__ __forceinline__ float warpSum(float v) {
    #pragma unroll
    for (int o = 16; o; o >>= 1) v += __shfl_xor_sync(0xffffffffu, v, o);
    return v;
}
__device__ __forceinline__ float warpMax(float v) {
    #pragma unroll
    for (int o = 16; o; o >>= 1) v = fmaxf(v, __shfl_xor_sync(0xffffffffu, v, o));
    return v;
}

__device__ __forceinline__ uint32_t rotl_(uint32_t v, int s) { return (v << s) | (v >> (32 - s)); }

// Threefry-2x32 with key = (0, 42)  == jax.random.key(42)
__device__ __forceinline__ void threefry_42(uint32_t x0, uint32_t x1, uint32_t& o0, uint32_t& o1) {
    const uint32_t k0 = 0u, k1 = 42u;
    const uint32_t k2 = 0u ^ 42u ^ 0x1BD11BDAu;
    x0 += k0; x1 += k1;
#define TF4(a,b,c,d, ka, kb, inc)                     \
    x0 += x1; x1 = rotl_(x1, a); x1 ^= x0;            \
    x0 += x1; x1 = rotl_(x1, b); x1 ^= x0;            \
    x0 += x1; x1 = rotl_(x1, c); x1 ^= x0;            \
    x0 += x1; x1 = rotl_(x1, d); x1 ^= x0;            \
    x0 += ka; x1 += kb + inc;
    TF4(13, 15, 26, 6,  k1, k2, 1u)
    TF4(17, 29, 16, 24, k2, k0, 2u)
    TF4(13, 15, 26, 6,  k0, k1, 3u)
    TF4(17, 29, 16, 24, k1, k2, 4u)
    TF4(13, 15, 26, 6,  k2, k0, 5u)
#undef TF4
    o0 = x0; o1 = x1;
}

// gumbel noise*0.05 for flat index into [16,1024,1024].
// JAX with jax_threefry_partitionable=True (default since 0.4.36+):
// per-element counter (hi32(i), lo32(i)) = (0, i); 32-bit bits = out0 ^ out1.
__device__ __forceinline__ float gumbel_noise(uint32_t idx) {
    uint32_t o0, o1;
    threefry_42(0u, idx, o0, o1);
    uint32_t bits = o0 ^ o1;
    float u = __uint_as_float((bits >> 9) | 0x3f800000u) - 1.0f;
    return -logf(-logf(u + 1e-20f) + 1e-20f) * 0.05f;
}

// ---------------- row sums of adj ----------------
__global__ void rowsum_kernel(const float* __restrict__ adj,
                              float* __restrict__ dis, float* __restrict__ rsinv) {
    int gr = blockIdx.x, t = threadIdx.x;
    float4 a4 = ((const float4*)(adj + ((size_t)gr << 10)))[t];
    float s = a4.x + a4.y + a4.z + a4.w;
    s = warpSum(s);
    __shared__ float sm[8];
    if ((t & 31) == 0) sm[t >> 5] = s;
    __syncthreads();
    if (t == 0) {
        float S = sm[0] + sm[1] + sm[2] + sm[3] + sm[4] + sm[5] + sm[6] + sm[7];
        dis[gr]   = rsqrtf(S + 1.0f);
        rsinv[gr] = 1.0f / S;
    }
}

// ---------------- dense GEMM: C[16384, Nout] = ep(X @ W^T + b) ----------------
// 128x128 block tile, 256 threads, 8x8 per thread. EP: 0=none,1=leaky,2=Z0.
template<int EP>
__global__ void __launch_bounds__(256)
dense_gemm(const float* __restrict__ X, int ldx,
           const float* __restrict__ W, int K,
           const float* __restrict__ bias,
           float* __restrict__ out, int ldo,
           float* __restrict__ zbuf) {
    __shared__ float As[16][132];
    __shared__ float Bs[16][132];
    const int t  = threadIdx.x;
    const int m0 = blockIdx.y << 7;
    const int n0 = blockIdx.x << 7;
    const int tx = t & 15, ty = t >> 4;
    const int lr = t >> 1;           // 0..127
    const int lk = (t & 1) << 3;     // 0 or 8

    float acc[8][8];
    #pragma unroll
    for (int i = 0; i < 8; i++)
        #pragma unroll
        for (int j = 0; j < 8; j++) acc[i][j] = 0.0f;

    const float* Ap = X + (size_t)(m0 + lr) * ldx + lk;
    const float* Bp = W + (size_t)(n0 + lr) * K + lk;

    for (int kt = 0; kt < K; kt += 16) {
        float4 av0 = *(const float4*)(Ap + kt);
        float4 av1 = *(const float4*)(Ap + kt + 4);
        float4 bv0 = *(const float4*)(Bp + kt);
        float4 bv1 = *(const float4*)(Bp + kt + 4);
        As[lk+0][lr]=av0.x; As[lk+1][lr]=av0.y; As[lk+2][lr]=av0.z; As[lk+3][lr]=av0.w;
        As[lk+4][lr]=av1.x; As[lk+5][lr]=av1.y; As[lk+6][lr]=av1.z; As[lk+7][lr]=av1.w;
        Bs[lk+0][lr]=bv0.x; Bs[lk+1][lr]=bv0.y; Bs[lk+2][lr]=bv0.z; Bs[lk+3][lr]=bv0.w;
        Bs[lk+4][lr]=bv1.x; Bs[lk+5][lr]=bv1.y; Bs[lk+6][lr]=bv1.z; Bs[lk+7][lr]=bv1.w;
        __syncthreads();
        #pragma unroll
        for (int k = 0; k < 16; k++) {
            float af[8], bf[8];
            *(float4*)(af)     = *(const float4*)&As[k][(ty<<3)];
            *(float4*)(af + 4) = *(const float4*)&As[k][(ty<<3) + 4];
            *(float4*)(bf)     = *(const float4*)&Bs[k][(tx<<3)];
            *(float4*)(bf + 4) = *(const float4*)&Bs[k][(tx<<3) + 4];
            #pragma unroll
            for (int i = 0; i < 8; i++)
                #pragma unroll
                for (int j = 0; j < 8; j++)
                    acc[i][j] = fmaf(af[i], bf[j], acc[i][j]);
        }
        __syncthreads();
    }

    #pragma unroll
    for (int i = 0; i < 8; i++) {
        int rg = m0 + (ty << 3) + i;
        #pragma unroll
        for (int j = 0; j < 8; j++) {
            int cg = n0 + (tx << 3) + j;
            float vv = acc[i][j] + __ldg(&bias[cg]);
            if (EP == 0) {
                out[(size_t)rg * ldo + cg] = vv;
            } else if (EP == 1) {
                out[(size_t)rg * ldo + cg] = lky(vv);
            } else {
                uint32_t idx = ((uint32_t)rg << 10) + (uint32_t)cg;
                float z = (tanhf(vv) * 40.0f + gumbel_noise(idx)) * 10.0f;
                zbuf[idx] = z;
            }
        }
    }
}

// ---------------- batched adjacency GEMM: C_b = adj_b @ U_b ----------------
// MODE 0: GCN  (B scaled by dis_j on load; out=leaky(dis_i*acc + dis_i^2*aux) -> hallc)
// MODE 1: applyP + diff (p=0.5(U+rsinv*acc) -> pout; |aux-p| -> hallc)
// MODE 2: applyP plain  (p -> pout)
template<int MODE>
__global__ void __launch_bounds__(256)
adj_gemm(const float* __restrict__ adj,
         const float* __restrict__ U, int ldu,
         const float* __restrict__ aux, int ldaux,
         const float* __restrict__ dis, const float* __restrict__ rsinv,
         float* __restrict__ pout, int ldp,
         float* __restrict__ hallc) {
    __shared__ float As[16][132];
    __shared__ float Bs[16][132];
    const int t  = threadIdx.x;
    const int b  = blockIdx.z;
    const int m0 = blockIdx.y << 7;
    const int n0 = blockIdx.x << 7;
    const int tx = t & 15, ty = t >> 4;
    const int lr = t >> 1, lk = (t & 1) << 3;     // A transpose-load
    const int bk = t >> 4, bnq = (t & 15) << 3;   // B direct-load

    float acc[8][8];
    #pragma unroll
    for (int i = 0; i < 8; i++)
        #pragma unroll
        for (int j = 0; j < 8; j++) acc[i][j] = 0.0f;

    const float* Ap = adj + ((size_t)b << 20) + (size_t)(m0 + lr) * NN + lk;

    for (int kt = 0; kt < NN; kt += 16) {
        float4 av0 = *(const float4*)(Ap + kt);
        float4 av1 = *(const float4*)(Ap + kt + 4);
        const float* Brow = U + (size_t)((b << 10) + kt + bk) * ldu + n0 + bnq;
        float4 bv0 = *(const float4*)(Brow);
        float4 bv1 = *(const float4*)(Brow + 4);
        if (MODE == 0) {
            float sc = dis[(b << 10) + kt + bk];
            bv0.x*=sc; bv0.y*=sc; bv0.z*=sc; bv0.w*=sc;
            bv1.x*=sc; bv1.y*=sc; bv1.z*=sc; bv1.w*=sc;
        }
        As[lk+0][lr]=av0.x; As[lk+1][lr]=av0.y; As[lk+2][lr]=av0.z; As[lk+3][lr]=av0.w;
        As[lk+4][lr]=av1.x; As[lk+5][lr]=av1.y; As[lk+6][lr]=av1.z; As[lk+7][lr]=av1.w;
        *(float4*)&Bs[bk][bnq]     = bv0;
        *(float4*)&Bs[bk][bnq + 4] = bv1;
        __syncthreads();
        #pragma unroll
        for (int k = 0; k < 16; k++) {
            float af[8], bf[8];
            *(float4*)(af)     = *(const float4*)&As[k][(ty<<3)];
            *(float4*)(af + 4) = *(const float4*)&As[k][(ty<<3) + 4];
            *(float4*)(bf)     = *(const float4*)&Bs[k][(tx<<3)];
            *(float4*)(bf + 4) = *(const float4*)&Bs[k][(tx<<3) + 4];
            #pragma unroll
            for (int i = 0; i < 8; i++)
                #pragma unroll
                for (int j = 0; j < 8; j++)
                    acc[i][j] = fmaf(af[i], bf[j], acc[i][j]);
        }
        __syncthreads();
    }

    #pragma unroll
    for (int i = 0; i < 8; i++) {
        int il = m0 + (ty << 3) + i;          // row within batch
        int gi = (b << 10) + il;              // global row
        #pragma unroll
        for (int j = 0; j < 8; j++) {
            int cg = n0 + (tx << 3) + j;
            size_t hix = ((size_t)b << 20) + ((size_t)il << 8) + cg;
            if (MODE == 0) {
                float di = dis[gi];
                float xv = aux[(size_t)gi * ldaux + cg];
                float g = di * acc[i][j] + di * di * xv;
                hallc[hix] = lky(g);
            } else {
                float uin = U[(size_t)gi * ldu + cg];
                float p = 0.5f * (uin + rsinv[gi] * acc[i][j]);
                pout[(size_t)gi * ldp + cg] = p;
                if (MODE == 1) {
                    float ax = aux[(size_t)gi * ldaux + cg];
                    hallc[hix] = fabsf(ax - p);
                }
            }
        }
    }
}

// ---------------- attention + channel mix ----------------
__global__ void attention_kernel(const float* __restrict__ Xl, int ldx,
                                 const float* __restrict__ hall,
                                 const float* __restrict__ a,
                                 float* __restrict__ hp) {
    int n = blockIdx.x, b = blockIdx.y, t = threadIdx.x;
    float xv = Xl[(size_t)((b << 10) + n) * ldx + t];
    float hv[4];
    size_t hbase = ((size_t)b << 20) + ((size_t)n << 8) + t;
    #pragma unroll
    for (int c = 0; c < 4; c++) hv[c] = hall[hbase + ((size_t)c << 18)];
    float a1 = a[t], a2 = a[256 + t];
    float p[5];
    p[0] = fmaxf(xv, 0.0f) * a1;
    #pragma unroll
    for (int c = 0; c < 4; c++) p[1 + c] = fmaxf(hv[c], 0.0f) * a2;

    __shared__ float sm[5][8];
    #pragma unroll
    for (int q = 0; q < 5; q++) {
        float s = warpSum(p[q]);
        if ((t & 31) == 0) sm[q][t >> 5] = s;
    }
    __syncthreads();
    float S[5];
    #pragma unroll
    for (int q = 0; q < 5; q++) {
        float s = sm[q][0];
        #pragma unroll
        for (int w = 1; w < 8; w++) s += sm[q][w];
        S[q] = s;
    }
    float e0 = S[0] + S[1], e1 = S[0] + S[2], e2 = S[0] + S[3], e3 = S[0] + S[4];
    float M = fmaxf(fmaxf(e0, e1), fmaxf(e2, e3));
    float w0 = __expf(e0 - M), w1 = __expf(e1 - M), w2 = __expf(e2 - M), w3 = __expf(e3 - M);
    float ws = w0 + w1 + w2 + w3;
    float o = w0 * hv[0] + w1 * hv[1] + w2 * hv[2] + w3 * hv[3];
    hp[(size_t)((b << 10) + n) * HH + t] = 0.25f * o / ws;
}

// ---------------- sinkhorn ----------------
__global__ void zero_uv(float* __restrict__ u, float* __restrict__ v) {
    int i = blockIdx.x * blockDim.x + threadIdx.x;
    if (i < NB * NN) { u[i] = 0.0f; v[i] = 0.0f; }
}

__global__ void row_lse(const float* __restrict__ Z0, const float* __restrict__ v,
                        float* __restrict__ u) {
    int gr = blockIdx.x, b = gr >> 10, t = threadIdx.x;
    float4 z4 = ((const float4*)(Z0 + ((size_t)gr << 10)))[t];
    float4 v4 = ((const float4*)(v + (b << 10)))[t];
    float a0 = z4.x - v4.x, a1 = z4.y - v4.y, a2 = z4.z - v4.z, a3 = z4.w - v4.w;
    float m = fmaxf(fmaxf(a0, a1), fmaxf(a2, a3));
    __shared__ float sm[8];
    m = warpMax(m);
    if ((t & 31) == 0) sm[t >> 5] = m;
    __syncthreads();
    float M = sm[0];
    #pragma unroll
    for (int i = 1; i < 8; i++) M = fmaxf(M, sm[i]);
    __syncthreads();
    float s = __expf(a0 - M) + __expf(a1 - M) + __expf(a2 - M) + __expf(a3 - M);
    s = warpSum(s);
    if ((t & 31) == 0) sm[t >> 5] = s;
    __syncthreads();
    if (t == 0) {
        float S = sm[0] + sm[1] + sm[2] + sm[3] + sm[4] + sm[5] + sm[6] + sm[7];
        u[gr] = M + __logf(S);
    }
}

__global__ void col_lse(const float* __restrict__ Z0, const float* __restrict__ u,
                        float* __restrict__ v) {
    int b = blockIdx.y, t = threadIdx.x;
    int jj = t & 63, seg = t >> 6;
    int j = (blockIdx.x << 6) + jj;
    __shared__ float us[1024];
    __shared__ float red[256];
    for (int i = t; i < 1024; i += 256) us[i] = u[(b << 10) + i];
    __syncthreads();
    const float* zb = Z0 + ((size_t)b << 20);
    float m = -INFINITY;
    int i0 = seg << 8;
    for (int i = i0; i < i0 + 256; i++)
        m = fmaxf(m, zb[((size_t)i << 10) + j] - us[i]);
    red[t] = m;
    __syncthreads();
    float M = fmaxf(fmaxf(red[jj], red[jj + 64]), fmaxf(red[jj + 128], red[jj + 192]));
    __syncthreads();
    float s = 0.0f;
    for (int i = i0; i < i0 + 256; i++)
        s += __expf(zb[((size_t)i << 10) + j] - us[i] - M);
    red[t] = s;
    __syncthreads();
    if (seg == 0) {
        float S = red[jj] + red[jj + 64] + red[jj + 128] + red[jj + 192];
        v[(b << 10) + j] = M + __logf(S);
    }
}

// P = exp(Z0-u-v); r = rowsum(P)
__global__ void row_expsum(const float* __restrict__ Z0, const float* __restrict__ u,
                           const float* __restrict__ v, float* __restrict__ P,
                           float* __restrict__ r) {
    int gr = blockIdx.x, b = gr >> 10, t = threadIdx.x;
    float uu = u[gr];
    float4 z4 = ((const float4*)(Z0 + ((size_t)gr << 10)))[t];
    float4 v4 = ((const float4*)(v + (b << 10)))[t];
    float4 e;
    e.x = __expf(z4.x - uu - v4.x);
    e.y = __expf(z4.y - uu - v4.y);
    e.z = __expf(z4.z - uu - v4.z);
    e.w = __expf(z4.w - uu - v4.w);
    ((float4*)(P + ((size_t)gr << 10)))[t] = e;
    float s = e.x + e.y + e.z + e.w;
    s = warpSum(s);
    __shared__ float sm[8];
    if ((t & 31) == 0) sm[t >> 5] = s;
    __syncthreads();
    if (t == 0)
        r[gr] = sm[0] + sm[1] + sm[2] + sm[3] + sm[4] + sm[5] + sm[6] + sm[7];
}

// c_j = sum_i P[i,j]/r_i
__global__ void col_divsum(const float* __restrict__ P, const float* __restrict__ r,
                           float* __restrict__ c) {
    int b = blockIdx.y, t = threadIdx.x;
    int jj = t & 63, seg = t >> 6;
    int j = (blockIdx.x << 6) + jj;
    __shared__ float ri[1024];
    __shared__ float red[256];
    for (int i = t; i < 1024; i += 256) ri[i] = 1.0f / r[(b << 10) + i];
    __syncthreads();
    const float* pb = P + ((size_t)b << 20);
    float s = 0.0f;
    int i0 = seg << 8;
    for (int i = i0; i < i0 + 256; i++)
        s += pb[((size_t)i << 10) + j] * ri[i];
    red[t] = s;
    __syncthreads();
    if (seg == 0)
        c[(b << 10) + j] = red[jj] + red[jj + 64] + red[jj + 128] + red[jj + 192];
}

__global__ void final_scale(float* __restrict__ P, const float* __restrict__ r,
                            const float* __restrict__ c) {
    size_t q = (size_t)blockIdx.x * blockDim.x + threadIdx.x;  // float4 index
    size_t flat = q << 2;
    int gr = (int)(flat >> 10);
    int b  = gr >> 10;
    int j  = (int)(flat & 1023);
    float rin = 1.0f / r[gr];
    float4 cc = *(const float4*)(c + (b << 10) + j);
    float4 p = ((float4*)P)[q];
    p.x = p.x * rin / cc.x;
    p.y = p.y * rin / cc.y;
    p.z = p.z * rin / cc.z;
    p.w = p.w * rin / cc.w;
    ((float4*)P)[q] = p;
}

// ---------------- launch ----------------
extern "C" void kernel_launch(void* const* d_in, const int* in_sizes, int n_in,
                              void* d_out, int out_size) {
    (void)in_sizes; (void)n_in; (void)out_size;
    const float* X    = (const float*)d_in[0];
    const float* adj  = (const float*)d_in[1];
    const float* w_in = (const float*)d_in[2];
    const float* b_in = (const float*)d_in[3];
    const float* cw1  = (const float*)d_in[4];
    const float* cb1  = (const float*)d_in[5];
    const float* cw2  = (const float*)d_in[6];
    const float* cb2  = (const float*)d_in[7];
    const float* ca   = (const float*)d_in[8];
    const float* m1w  = (const float*)d_in[9];
    const float* m1b  = (const float*)d_in[10];
    const float* m2w  = (const float*)d_in[11];
    const float* m2b  = (const float*)d_in[12];

    float* outP = (float*)d_out;
    float* Z0   = outP + (size_t)NB * NN * NN;

    float *hall, *hcat, *t0, *t1, *t2, *hp, *ht, *m1, *dis, *rsinv, *u, *v, *r, *c;
    cudaGetSymbolAddress((void**)&hall, g_hall);
    cudaGetSymbolAddress((void**)&hcat, g_hcat);
    cudaGetSymbolAddress((void**)&t0, g_t0);
    cudaGetSymbolAddress((void**)&t1, g_t1);
    cudaGetSymbolAddress((void**)&t2, g_t2);
    cudaGetSymbolAddress((void**)&hp, g_hp);
    cudaGetSymbolAddress((void**)&ht, g_ht);
    cudaGetSymbolAddress((void**)&m1, g_m1);
    cudaGetSymbolAddress((void**)&dis, g_dis);
    cudaGetSymbolAddress((void**)&rsinv, g_rsinv);
    cudaGetSymbolAddress((void**)&u, g_u);
    cudaGetSymbolAddress((void**)&v, g_v);
    cudaGetSymbolAddress((void**)&r, g_r);
    cudaGetSymbolAddress((void**)&c, g_c);

    const size_t CH = (size_t)NN * HH;  // hall channel stride

    rowsum_kernel<<<NB * NN, 256>>>(adj, dis, rsinv);

    // h0 = X @ w_in^T + b_in  -> hcat slice 0 (ld 768)
    dense_gemm<0><<<dim3(2, 128), 256>>>(X, 128, w_in, 128, b_in, hcat, LH, nullptr);

    for (int l = 0; l < 2; l++) {
        const float* Xl = hcat + l * HH;   // ld LH
        dim3 ag(2, 8, NB);
        // c0: leaky(A_hat @ Xl)
        adj_gemm<0><<<ag, 256>>>(adj, Xl, LH, Xl, LH, dis, rsinv, nullptr, 0, hall + 0 * CH);
        // P1 = applyP(Xl); c1 = |Xl - P1|
        adj_gemm<1><<<ag, 256>>>(adj, Xl, LH, Xl, LH, dis, rsinv, t0, HH, hall + 1 * CH);
        // P2 = applyP(P1); c2 = |P1 - P2|
        adj_gemm<1><<<ag, 256>>>(adj, t0, HH, t0, HH, dis, rsinv, t1, HH, hall + 2 * CH);
        // P3 = applyP(P2)
        adj_gemm<2><<<ag, 256>>>(adj, t1, HH, nullptr, 0, dis, rsinv, t2, HH, nullptr);
        // P4 = applyP(P3); c3 = |P2 - P4|
        adj_gemm<1><<<ag, 256>>>(adj, t2, HH, t1, HH, dis, rsinv, t0, HH, hall + 3 * CH);

        attention_kernel<<<dim3(NN, NB), 256>>>(Xl, LH, hall, ca + l * 2 * HH, hp);

        dense_gemm<1><<<dim3(2, 128), 256>>>(hp, HH, cw1 + (size_t)l * HH * HH, HH,
                                             cb1 + l * HH, ht, HH, nullptr);
        dense_gemm<1><<<dim3(2, 128), 256>>>(ht, HH, cw2 + (size_t)l * HH * HH, HH,
                                             cb2 + l * HH, hcat + (l + 1) * HH, LH, nullptr);
    }

    // mlp1: leaky(hcat @ mlp1_w^T + b)
    dense_gemm<1><<<dim3(2, 128), 256>>>(hcat, LH, m1w, LH, m1b, m1, HH, nullptr);
    // mlp2 + tanh*40 + gumbel -> Z0 (gsinit output)
    dense_gemm<2><<<dim3(8, 128), 256>>>(m1, HH, m2w, HH, m2b, nullptr, 0, Z0);

    // sinkhorn (potentials form)
    zero_uv<<<64, 256>>>(u, v);
    for (int it = 0; it < 20; it++) {
        row_lse<<<NB * NN, 256>>>(Z0, v, u);
        col_lse<<<dim3(16, NB), 256>>>(Z0, u, v);
    }
    row_expsum<<<NB * NN, 256>>>(Z0, u, v, outP, r);
    col_divsum<<<dim3(16, NB), 256>>>(outP, r, c);
    final_scale<<<16384, 256>>>(outP, r, c);
}

// round 5
// speedup vs baseline: 1.4267x; 1.4267x over previous
#include <cuda_runtime.h>
#include <cuda_fp16.h>
#include <cstdint>
#include <math.h>

#define NB 16
#define NN 1024
#define HH 256
#define LH 768          // H*(1+L) = 768

// ---------------- scratch (__device__ globals; no cudaMalloc allowed) ----------------
__device__ float g_hall[(size_t)NB * 4 * NN * HH];   // [b][c][n][h]
__device__ float g_hcat[(size_t)NB * NN * LH];       // [b*n][768]  (h0|h1|h2)
__device__ float g_t0[(size_t)NB * NN * HH];
__device__ float g_t1[(size_t)NB * NN * HH];
__device__ float g_t2[(size_t)NB * NN * HH];
__device__ float g_hp[(size_t)NB * NN * HH];         // h_prime
__device__ float g_ht[(size_t)NB * NN * HH];         // after w1
__device__ float g_m1[(size_t)NB * NN * HH];         // after mlp1
__device__ float g_dis[NB * NN];                     // (rowsum(adj)+1)^-0.5
__device__ float g_rsinv[NB * NN];                   // 1/rowsum(adj)
__device__ float g_u[NB * NN];
__device__ float g_v[NB * NN];
__device__ float g_r[NB * NN];
__device__ float g_c[NB * NN];

// fp16 split operands
__device__ __half g_adjH[(size_t)NB * NN * NN];      // 32MB
__device__ __half g_adjL[(size_t)NB * NN * NN];
__device__ __half g_xlH[(size_t)NB * NN * HH];
__device__ __half g_xlL[(size_t)NB * NN * HH];
__device__ __half g_xsH[(size_t)NB * NN * HH];
__device__ __half g_xsL[(size_t)NB * NN * HH];
__device__ __half g_p0H[(size_t)NB * NN * HH];
__device__ __half g_p0L[(size_t)NB * NN * HH];
__device__ __half g_p1H[(size_t)NB * NN * HH];
__device__ __half g_p1L[(size_t)NB * NN * HH];
__device__ __half g_p2H[(size_t)NB * NN * HH];
__device__ __half g_p2L[(size_t)NB * NN * HH];

#define BSCALE 256.0f
#define BINV   (1.0f / 256.0f)

// ---------------- helpers ----------------
__device__ __forceinline__ float lky(float x) { return x > 0.0f ? x : 0.01f * x; }

__device__ __forceinline__ float warpSum(float v) {
    #pragma unroll
    for (int o = 16; o; o >>= 1) v += __shfl_xor_sync(0xffffffffu, v, o);
    return v;
}
__device__ __forceinline__ float warpMax(float v) {
    #pragma unroll
    for (int o = 16; o; o >>= 1) v = fmaxf(v, __shfl_xor_sync(0xffffffffu, v, o));
    return v;
}

__device__ __forceinline__ uint32_t rotl_(uint32_t v, int s) { return (v << s) | (v >> (32 - s)); }

// Threefry-2x32 with key = (0, 42)  == jax.random.key(42)
__device__ __forceinline__ void threefry_42(uint32_t x0, uint32_t x1, uint32_t& o0, uint32_t& o1) {
    const uint32_t k0 = 0u, k1 = 42u;
    const uint32_t k2 = 0u ^ 42u ^ 0x1BD11BDAu;
    x0 += k0; x1 += k1;
#define TF4(a,b,c,d, ka, kb, inc)                     \
    x0 += x1; x1 = rotl_(x1, a); x1 ^= x0;            \
    x0 += x1; x1 = rotl_(x1, b); x1 ^= x0;            \
    x0 += x1; x1 = rotl_(x1, c); x1 ^= x0;            \
    x0 += x1; x1 = rotl_(x1, d); x1 ^= x0;            \
    x0 += ka; x1 += kb + inc;
    TF4(13, 15, 26, 6,  k1, k2, 1u)
    TF4(17, 29, 16, 24, k2, k0, 2u)
    TF4(13, 15, 26, 6,  k0, k1, 3u)
    TF4(17, 29, 16, 24, k1, k2, 4u)
    TF4(13, 15, 26, 6,  k2, k0, 5u)
#undef TF4
    o0 = x0; o1 = x1;
}

// gumbel noise*0.05, jax_threefry_partitionable layout: counter (0, idx), bits = o0^o1
__device__ __forceinline__ float gumbel_noise(uint32_t idx) {
    uint32_t o0, o1;
    threefry_42(0u, idx, o0, o1);
    uint32_t bits = o0 ^ o1;
    float u = __uint_as_float((bits >> 9) | 0x3f800000u) - 1.0f;
    return -logf(-logf(u + 1e-20f) + 1e-20f) * 0.05f;
}

// ---------------- tensor-core primitives ----------------
__device__ __forceinline__ uint32_t s2u(const void* p) {
    return (uint32_t)__cvta_generic_to_shared(p);
}
__device__ __forceinline__ void cpa16(uint32_t s, const void* g) {
    asm volatile("cp.async.cg.shared.global [%0], [%1], 16;" :: "r"(s), "l"(g));
}
__device__ __forceinline__ void cpa_commit() {
    asm volatile("cp.async.commit_group;" ::: "memory");
}
template<int N>
__device__ __forceinline__ void cpa_wait() {
    asm volatile("cp.async.wait_group %0;" :: "n"(N) : "memory");
}
__device__ __forceinline__ void ldmA4(uint32_t a, uint32_t* r) {
    asm volatile("ldmatrix.sync.aligned.m8n8.x4.shared.b16 {%0,%1,%2,%3}, [%4];"
        : "=r"(r[0]), "=r"(r[1]), "=r"(r[2]), "=r"(r[3]) : "r"(a));
}
__device__ __forceinline__ void ldmB4T(uint32_t a, uint32_t* r) {
    asm volatile("ldmatrix.sync.aligned.m8n8.x4.trans.shared.b16 {%0,%1,%2,%3}, [%4];"
        : "=r"(r[0]), "=r"(r[1]), "=r"(r[2]), "=r"(r[3]) : "r"(a));
}
__device__ __forceinline__ void mma16816(float* d, const uint32_t* A, const uint32_t* b) {
    asm volatile("mma.sync.aligned.m16n8k16.row.col.f32.f16.f16.f32 "
        "{%0,%1,%2,%3},{%4,%5,%6,%7},{%8,%9},{%0,%1,%2,%3};"
        : "+f"(d[0]), "+f"(d[1]), "+f"(d[2]), "+f"(d[3])
        : "r"(A[0]), "r"(A[1]), "r"(A[2]), "r"(A[3]), "r"(b[0]), "r"(b[1]));
}

// ---------------- converters ----------------
// adj -> fp16 hi/lo (row-major, no scale; values in [0,1])
__global__ void convert_adj(const float* __restrict__ adj,
                            __half* __restrict__ aH, __half* __restrict__ aL) {
    size_t gid = (size_t)blockIdx.x * 256 + threadIdx.x;   // over 4M float4s
    float4 a = ((const float4*)adj)[gid];
    __half2 h01 = __floats2half2_rn(a.x, a.y);
    __half2 h23 = __floats2half2_rn(a.z, a.w);
    __half2 l01 = __floats2half2_rn(a.x - __low2float(h01), a.y - __high2float(h01));
    __half2 l23 = __floats2half2_rn(a.z - __low2float(h23), a.w - __high2float(h23));
    ((__half2*)aH)[gid * 2]     = h01;
    ((__half2*)aH)[gid * 2 + 1] = h23;
    ((__half2*)aL)[gid * 2]     = l01;
    ((__half2*)aL)[gid * 2 + 1] = l23;
}

// hcat slice -> xl pair (256*x) and xs pair (256*dis*x)
__global__ void convert_x(const float* __restrict__ Xl, const float* __restrict__ dis,
                          __half* __restrict__ xlH, __half* __restrict__ xlL,
                          __half* __restrict__ xsH, __half* __restrict__ xsL) {
    int gid = blockIdx.x * 256 + threadIdx.x;   // over 16384*256
    int r = gid >> 8, c = gid & 255;
    float x = Xl[(size_t)r * LH + c];
    float xl = x * BSCALE;
    float xs = xl * dis[r];
    __half h1 = __float2half_rn(xl);
    __half h2 = __float2half_rn(xs);
    xlH[gid] = h1; xlL[gid] = __float2half_rn(xl - __half2float(h1));
    xsH[gid] = h2; xsL[gid] = __float2half_rn(xs - __half2float(h2));
}

// ---------------- row sums of adj ----------------
__global__ void rowsum_kernel(const float* __restrict__ adj,
                              float* __restrict__ dis, float* __restrict__ rsinv) {
    int gr = blockIdx.x, t = threadIdx.x;
    float4 a4 = ((const float4*)(adj + ((size_t)gr << 10)))[t];
    float s = a4.x + a4.y + a4.z + a4.w;
    s = warpSum(s);
    __shared__ float sm[8];
    if ((t & 31) == 0) sm[t >> 5] = s;
    __syncthreads();
    if (t == 0) {
        float S = sm[0] + sm[1] + sm[2] + sm[3] + sm[4] + sm[5] + sm[6] + sm[7];
        dis[gr]   = rsqrtf(S + 1.0f);
        rsinv[gr] = 1.0f / S;
    }
}

// ---------------- tensor-core adjacency GEMM: C_b = adj_b @ B_b ----------------
// fp16 two-term split (hi+lo, 3 mma combos), fp32 accumulate. B operands pre-scaled by 256.
// MODE 0: GCN:  g = leaky(dis_i*acc + dis_i^2*aux)              -> hallc
// MODE 1: p = 0.5(U32 + rsinv_i*acc) -> pout + fp16 pair; |aux - p| -> hallc
// MODE 2: p -> pout + fp16 pair only
// smem per stage: AH[128][40] AL[128][40] BH[32][136] BL[32][136] halfs (37888 B), 2 stages
template<int MODE>
__global__ void __launch_bounds__(256, 1)
adjmma(const __half* __restrict__ adjH, const __half* __restrict__ adjL,
       const __half* __restrict__ bH, const __half* __restrict__ bL,
       const float* __restrict__ U32, int ldu,
       const float* __restrict__ aux, int ldaux,
       const float* __restrict__ dis, const float* __restrict__ rsinv,
       float* __restrict__ pout, int ldp,
       __half* __restrict__ poutH, __half* __restrict__ poutL,
       float* __restrict__ hallc) {
    extern __shared__ char smx[];
    const uint32_t sbase = s2u(smx);
    const int t = threadIdx.x;
    const int b = blockIdx.z;
    const int m0 = blockIdx.y << 7;
    const int n0 = blockIdx.x << 7;
    const int w = t >> 5, lane = t & 31;
    const int wm = w >> 1, wn = w & 1;
    const int lr16 = lane & 15, lhi = lane >> 4;

    float acc[2][8][4];
    #pragma unroll
    for (int mi = 0; mi < 2; mi++)
        #pragma unroll
        for (int nj = 0; nj < 8; nj++)
            #pragma unroll
            for (int ci = 0; ci < 4; ci++) acc[mi][nj][ci] = 0.0f;

    const int ar = t >> 2,  asg = t & 3;    // A loader: row, 16B-seg (of 4)
    const int bk = t >> 4,  bsg = t & 15;   // B loader: k-row(0..15 +16*it), seg (of 16)

    // ---- issue one K=32 chunk into stage st ----
    auto issue = [&](int kt, int st) {
        uint32_t AHb = sbase + st * 37888;
        uint32_t ALb = AHb + 10240;
        uint32_t BHb = ALb + 10240;
        uint32_t BLb = BHb + 8704;
        #pragma unroll
        for (int it = 0; it < 2; it++) {
            int r = ar + (it << 6);            // 0..127
            size_t gA = ((size_t)b << 20) + ((size_t)(m0 + r) << 10) + (kt << 5) + (asg << 3);
            uint32_t sA = (uint32_t)(r * 80 + (asg << 4));
            cpa16(AHb + sA, adjH + gA);
            cpa16(ALb + sA, adjL + gA);
            int k = bk + (it << 4);            // 0..31
            size_t gB = ((size_t)((b << 10) + (kt << 5) + k) << 8) + n0 + (bsg << 3);
            uint32_t sB = (uint32_t)(k * 272 + (bsg << 4));
            cpa16(BHb + sB, bH + gB);
            cpa16(BLb + sB, bL + gB);
        }
        cpa_commit();
    };

    issue(0, 0);
    for (int kt = 0; kt < 32; kt++) {
        if (kt < 31) { issue(kt + 1, (kt + 1) & 1); cpa_wait<1>(); }
        else         { cpa_wait<0>(); }
        __syncthreads();

        int st = kt & 1;
        uint32_t AHb = sbase + st * 37888;
        uint32_t ALb = AHb + 10240;
        uint32_t BHb = ALb + 10240;
        uint32_t BLb = BHb + 8704;

        #pragma unroll
        for (int kk = 0; kk < 32; kk += 16) {
            uint32_t aH[2][4], aL[2][4];
            uint32_t cc2 = (uint32_t)((kk + (lhi << 3)) << 1);
            #pragma unroll
            for (int mi = 0; mi < 2; mi++) {
                uint32_t ro = (uint32_t)((wm * 32 + mi * 16 + lr16) * 80);
                ldmA4(AHb + ro + cc2, aH[mi]);
                ldmA4(ALb + ro + cc2, aL[mi]);
            }
            uint32_t bHf[8][2], bLf[8][2];
            #pragma unroll
            for (int np = 0; np < 4; np++) {
                uint32_t ko = (uint32_t)((kk + lr16) * 272);
                uint32_t nc = (uint32_t)((wn * 64 + np * 16 + (lhi << 3)) << 1);
                uint32_t r4[4];
                ldmB4T(BHb + ko + nc, r4);
                bHf[np*2][0] = r4[0]; bHf[np*2][1] = r4[1];
                bHf[np*2+1][0] = r4[2]; bHf[np*2+1][1] = r4[3];
                ldmB4T(BLb + ko + nc, r4);
                bLf[np*2][0] = r4[0]; bLf[np*2][1] = r4[1];
                bLf[np*2+1][0] = r4[2]; bLf[np*2+1][1] = r4[3];
            }
            #pragma unroll
            for (int mi = 0; mi < 2; mi++)
                #pragma unroll
                for (int nj = 0; nj < 8; nj++) {
                    mma16816(acc[mi][nj], aH[mi], bHf[nj]);
                    mma16816(acc[mi][nj], aH[mi], bLf[nj]);
                    mma16816(acc[mi][nj], aL[mi], bHf[nj]);
                }
        }
        __syncthreads();
    }

    // ---- epilogue ----
    const int g8 = lane >> 2, t4 = lane & 3;
    #pragma unroll
    for (int mi = 0; mi < 2; mi++)
        #pragma unroll
        for (int nj = 0; nj < 8; nj++)
            #pragma unroll
            for (int ci = 0; ci < 4; ci++) {
                int il = m0 + wm * 32 + mi * 16 + g8 + ((ci >> 1) << 3);
                int cg = n0 + wn * 64 + nj * 8 + (t4 << 1) + (ci & 1);
                int gi = (b << 10) + il;
                float a = acc[mi][nj][ci] * BINV;
                size_t hix = ((size_t)b << 20) + ((size_t)il << 8) + cg;
                if (MODE == 0) {
                    float di = dis[gi];
                    float xv = aux[(size_t)gi * ldaux + cg];
                    hallc[hix] = lky(di * a + di * di * xv);
                } else {
                    float p = 0.5f * (U32[(size_t)gi * ldu + cg] + rsinv[gi] * a);
                    pout[(size_t)gi * ldp + cg] = p;
                    float ps = p * BSCALE;
                    __half ph = __float2half_rn(ps);
                    size_t pix = ((size_t)gi << 8) + cg;
                    poutH[pix] = ph;
                    poutL[pix] = __float2half_rn(ps - __half2float(ph));
                    if (MODE == 1) {
                        float ax = aux[(size_t)gi * ldaux + cg];
                        hallc[hix] = fabsf(ax - p);
                    }
                }
            }
}

// ---------------- dense GEMM (FFMA): C[16384, Nout] = ep(X @ W^T + b) ----------------
template<int EP>
__global__ void __launch_bounds__(256)
dense_gemm(const float* __restrict__ X, int ldx,
           const float* __restrict__ W, int K,
           const float* __restrict__ bias,
           float* __restrict__ out, int ldo,
           float* __restrict__ zbuf) {
    __shared__ float As[16][132];
    __shared__ float Bs[16][132];
    const int t  = threadIdx.x;
    const int m0 = blockIdx.y << 7;
    const int n0 = blockIdx.x << 7;
    const int tx = t & 15, ty = t >> 4;
    const int lr = t >> 1;
    const int lk = (t & 1) << 3;

    float acc[8][8];
    #pragma unroll
    for (int i = 0; i < 8; i++)
        #pragma unroll
        for (int j = 0; j < 8; j++) acc[i][j] = 0.0f;

    const float* Ap = X + (size_t)(m0 + lr) * ldx + lk;
    const float* Bp = W + (size_t)(n0 + lr) * K + lk;

    for (int kt = 0; kt < K; kt += 16) {
        float4 av0 = *(const float4*)(Ap + kt);
        float4 av1 = *(const float4*)(Ap + kt + 4);
        float4 bv0 = *(const float4*)(Bp + kt);
        float4 bv1 = *(const float4*)(Bp + kt + 4);
        As[lk+0][lr]=av0.x; As[lk+1][lr]=av0.y; As[lk+2][lr]=av0.z; As[lk+3][lr]=av0.w;
        As[lk+4][lr]=av1.x; As[lk+5][lr]=av1.y; As[lk+6][lr]=av1.z; As[lk+7][lr]=av1.w;
        Bs[lk+0][lr]=bv0.x; Bs[lk+1][lr]=bv0.y; Bs[lk+2][lr]=bv0.z; Bs[lk+3][lr]=bv0.w;
        Bs[lk+4][lr]=bv1.x; Bs[lk+5][lr]=bv1.y; Bs[lk+6][lr]=bv1.z; Bs[lk+7][lr]=bv1.w;
        __syncthreads();
        #pragma unroll
        for (int k = 0; k < 16; k++) {
            float af[8], bf[8];
            *(float4*)(af)     = *(const float4*)&As[k][(ty<<3)];
            *(float4*)(af + 4) = *(const float4*)&As[k][(ty<<3) + 4];
            *(float4*)(bf)     = *(const float4*)&Bs[k][(tx<<3)];
            *(float4*)(bf + 4) = *(const float4*)&Bs[k][(tx<<3) + 4];
            #pragma unroll
            for (int i = 0; i < 8; i++)
                #pragma unroll
                for (int j = 0; j < 8; j++)
                    acc[i][j] = fmaf(af[i], bf[j], acc[i][j]);
        }
        __syncthreads();
    }

    #pragma unroll
    for (int i = 0; i < 8; i++) {
        int rg = m0 + (ty << 3) + i;
        #pragma unroll
        for (int j = 0; j < 8; j++) {
            int cg = n0 + (tx << 3) + j;
            float vv = acc[i][j] + __ldg(&bias[cg]);
            if (EP == 0) {
                out[(size_t)rg * ldo + cg] = vv;
            } else if (EP == 1) {
                out[(size_t)rg * ldo + cg] = lky(vv);
            } else {
                uint32_t idx = ((uint32_t)rg << 10) + (uint32_t)cg;
                float z = (tanhf(vv) * 40.0f + gumbel_noise(idx)) * 10.0f;
                zbuf[idx] = z;
            }
        }
    }
}

// ---------------- attention + channel mix ----------------
__global__ void attention_kernel(const float* __restrict__ Xl, int ldx,
                                 const float* __restrict__ hall,
                                 const float* __restrict__ a,
                                 float* __restrict__ hp) {
    int n = blockIdx.x, b = blockIdx.y, t = threadIdx.x;
    float xv = Xl[(size_t)((b << 10) + n) * ldx + t];
    float hv[4];
    size_t hbase = ((size_t)b << 20) + ((size_t)n << 8) + t;
    #pragma unroll
    for (int c = 0; c < 4; c++) hv[c] = hall[hbase + ((size_t)c << 18)];
    float a1 = a[t], a2 = a[256 + t];
    float p[5];
    p[0] = fmaxf(xv, 0.0f) * a1;
    #pragma unroll
    for (int c = 0; c < 4; c++) p[1 + c] = fmaxf(hv[c], 0.0f) * a2;

    __shared__ float sm[5][8];
    #pragma unroll
    for (int q = 0; q < 5; q++) {
        float s = warpSum(p[q]);
        if ((t & 31) == 0) sm[q][t >> 5] = s;
    }
    __syncthreads();
    float S[5];
    #pragma unroll
    for (int q = 0; q < 5; q++) {
        float s = sm[q][0];
        #pragma unroll
        for (int w = 1; w < 8; w++) s += sm[q][w];
        S[q] = s;
    }
    float e0 = S[0] + S[1], e1 = S[0] + S[2], e2 = S[0] + S[3], e3 = S[0] + S[4];
    float M = fmaxf(fmaxf(e0, e1), fmaxf(e2, e3));
    float w0 = __expf(e0 - M), w1 = __expf(e1 - M), w2 = __expf(e2 - M), w3 = __expf(e3 - M);
    float ws = w0 + w1 + w2 + w3;
    float o = w0 * hv[0] + w1 * hv[1] + w2 * hv[2] + w3 * hv[3];
    hp[(size_t)((b << 10) + n) * HH + t] = 0.25f * o / ws;
}

// ---------------- sinkhorn ----------------
__global__ void zero_uv(float* __restrict__ u, float* __restrict__ v) {
    int i = blockIdx.x * blockDim.x + threadIdx.x;
    if (i < NB * NN) { u[i] = 0.0f; v[i] = 0.0f; }
}

__global__ void row_lse(const float* __restrict__ Z0, const float* __restrict__ v,
                        float* __restrict__ u) {
    int gr = blockIdx.x, b = gr >> 10, t = threadIdx.x;
    float4 z4 = ((const float4*)(Z0 + ((size_t)gr << 10)))[t];
    float4 v4 = ((const float4*)(v + (b << 10)))[t];
    float a0 = z4.x - v4.x, a1 = z4.y - v4.y, a2 = z4.z - v4.z, a3 = z4.w - v4.w;
    float m = fmaxf(fmaxf(a0, a1), fmaxf(a2, a3));
    __shared__ float sm[8];
    m = warpMax(m);
    if ((t & 31) == 0) sm[t >> 5] = m;
    __syncthreads();
    float M = sm[0];
    #pragma unroll
    for (int i = 1; i < 8; i++) M = fmaxf(M, sm[i]);
    __syncthreads();
    float s = __expf(a0 - M) + __expf(a1 - M) + __expf(a2 - M) + __expf(a3 - M);
    s = warpSum(s);
    if ((t & 31) == 0) sm[t >> 5] = s;
    __syncthreads();
    if (t == 0) {
        float S = sm[0] + sm[1] + sm[2] + sm[3] + sm[4] + sm[5] + sm[6] + sm[7];
        u[gr] = M + __logf(S);
    }
}

__global__ void col_lse(const float* __restrict__ Z0, const float* __restrict__ u,
                        float* __restrict__ v) {
    int b = blockIdx.y, t = threadIdx.x;
    int jj = t & 63, seg = t >> 6;
    int j = (blockIdx.x << 6) + jj;
    __shared__ float us[1024];
    __shared__ float red[256];
    for (int i = t; i < 1024; i += 256) us[i] = u[(b << 10) + i];
    __syncthreads();
    const float* zb = Z0 + ((size_t)b << 20);
    float m = -INFINITY;
    int i0 = seg << 8;
    for (int i = i0; i < i0 + 256; i++)
        m = fmaxf(m, zb[((size_t)i << 10) + j] - us[i]);
    red[t] = m;
    __syncthreads();
    float M = fmaxf(fmaxf(red[jj], red[jj + 64]), fmaxf(red[jj + 128], red[jj + 192]));
    __syncthreads();
    float s = 0.0f;
    for (int i = i0; i < i0 + 256; i++)
        s += __expf(zb[((size_t)i << 10) + j] - us[i] - M);
    red[t] = s;
    __syncthreads();
    if (seg == 0) {
        float S = red[jj] + red[jj + 64] + red[jj + 128] + red[jj + 192];
        v[(b << 10) + j] = M + __logf(S);
    }
}

__global__ void row_expsum(const float* __restrict__ Z0, const float* __restrict__ u,
                           const float* __restrict__ v, float* __restrict__ P,
                           float* __restrict__ r) {
    int gr = blockIdx.x, b = gr >> 10, t = threadIdx.x;
    float uu = u[gr];
    float4 z4 = ((const float4*)(Z0 + ((size_t)gr << 10)))[t];
    float4 v4 = ((const float4*)(v + (b << 10)))[t];
    float4 e;
    e.x = __expf(z4.x - uu - v4.x);
    e.y = __expf(z4.y - uu - v4.y);
    e.z = __expf(z4.z - uu - v4.z);
    e.w = __expf(z4.w - uu - v4.w);
    ((float4*)(P + ((size_t)gr << 10)))[t] = e;
    float s = e.x + e.y + e.z + e.w;
    s = warpSum(s);
    __shared__ float sm[8];
    if ((t & 31) == 0) sm[t >> 5] = s;
    __syncthreads();
    if (t == 0)
        r[gr] = sm[0] + sm[1] + sm[2] + sm[3] + sm[4] + sm[5] + sm[6] + sm[7];
}

__global__ void col_divsum(const float* __restrict__ P, const float* __restrict__ r,
                           float* __restrict__ c) {
    int b = blockIdx.y, t = threadIdx.x;
    int jj = t & 63, seg = t >> 6;
    int j = (blockIdx.x << 6) + jj;
    __shared__ float ri[1024];
    __shared__ float red[256];
    for (int i = t; i < 1024; i += 256) ri[i] = 1.0f / r[(b << 10) + i];
    __syncthreads();
    const float* pb = P + ((size_t)b << 20);
    float s = 0.0f;
    int i0 = seg << 8;
    for (int i = i0; i < i0 + 256; i++)
        s += pb[((size_t)i << 10) + j] * ri[i];
    red[t] = s;
    __syncthreads();
    if (seg == 0)
        c[(b << 10) + j] = red[jj] + red[jj + 64] + red[jj + 128] + red[jj + 192];
}

__global__ void final_scale(float* __restrict__ P, const float* __restrict__ r,
                            const float* __restrict__ c) {
    size_t q = (size_t)blockIdx.x * blockDim.x + threadIdx.x;
    size_t flat = q << 2;
    int gr = (int)(flat >> 10);
    int b  = gr >> 10;
    int j  = (int)(flat & 1023);
    float rin = 1.0f / r[gr];
    float4 cc = *(const float4*)(c + (b << 10) + j);
    float4 p = ((float4*)P)[q];
    p.x = p.x * rin / cc.x;
    p.y = p.y * rin / cc.y;
    p.z = p.z * rin / cc.z;
    p.w = p.w * rin / cc.w;
    ((float4*)P)[q] = p;
}

// ---------------- launch ----------------
extern "C" void kernel_launch(void* const* d_in, const int* in_sizes, int n_in,
                              void* d_out, int out_size) {
    (void)in_sizes; (void)n_in; (void)out_size;
    const float* X    = (const float*)d_in[0];
    const float* adj  = (const float*)d_in[1];
    const float* w_in = (const float*)d_in[2];
    const float* b_in = (const float*)d_in[3];
    const float* cw1  = (const float*)d_in[4];
    const float* cb1  = (const float*)d_in[5];
    const float* cw2  = (const float*)d_in[6];
    const float* cb2  = (const float*)d_in[7];
    const float* ca   = (const float*)d_in[8];
    const float* m1w  = (const float*)d_in[9];
    const float* m1b  = (const float*)d_in[10];
    const float* m2w  = (const float*)d_in[11];
    const float* m2b  = (const float*)d_in[12];

    float* outP = (float*)d_out;
    float* Z0   = outP + (size_t)NB * NN * NN;

    float *hall, *hcat, *t0, *t1, *t2, *hp, *ht, *m1, *dis, *rsinv, *u, *v, *r, *c;
    __half *adjH, *adjL, *xlH, *xlL, *xsH, *xsL, *p0H, *p0L, *p1H, *p1L, *p2H, *p2L;
    cudaGetSymbolAddress((void**)&hall, g_hall);
    cudaGetSymbolAddress((void**)&hcat, g_hcat);
    cudaGetSymbolAddress((void**)&t0, g_t0);
    cudaGetSymbolAddress((void**)&t1, g_t1);
    cudaGetSymbolAddress((void**)&t2, g_t2);
    cudaGetSymbolAddress((void**)&hp, g_hp);
    cudaGetSymbolAddress((void**)&ht, g_ht);
    cudaGetSymbolAddress((void**)&m1, g_m1);
    cudaGetSymbolAddress((void**)&dis, g_dis);
    cudaGetSymbolAddress((void**)&rsinv, g_rsinv);
    cudaGetSymbolAddress((void**)&u, g_u);
    cudaGetSymbolAddress((void**)&v, g_v);
    cudaGetSymbolAddress((void**)&r, g_r);
    cudaGetSymbolAddress((void**)&c, g_c);
    cudaGetSymbolAddress((void**)&adjH, g_adjH);
    cudaGetSymbolAddress((void**)&adjL, g_adjL);
    cudaGetSymbolAddress((void**)&xlH, g_xlH);
    cudaGetSymbolAddress((void**)&xlL, g_xlL);
    cudaGetSymbolAddress((void**)&xsH, g_xsH);
    cudaGetSymbolAddress((void**)&xsL, g_xsL);
    cudaGetSymbolAddress((void**)&p0H, g_p0H);
    cudaGetSymbolAddress((void**)&p0L, g_p0L);
    cudaGetSymbolAddress((void**)&p1H, g_p1H);
    cudaGetSymbolAddress((void**)&p1L, g_p1L);
    cudaGetSymbolAddress((void**)&p2H, g_p2H);
    cudaGetSymbolAddress((void**)&p2L, g_p2L);

    const int SMEM = 75776;
    cudaFuncSetAttribute(adjmma<0>, cudaFuncAttributeMaxDynamicSharedMemorySize, SMEM);
    cudaFuncSetAttribute(adjmma<1>, cudaFuncAttributeMaxDynamicSharedMemorySize, SMEM);
    cudaFuncSetAttribute(adjmma<2>, cudaFuncAttributeMaxDynamicSharedMemorySize, SMEM);

    const size_t CH = (size_t)NN * HH;  // hall channel stride

    rowsum_kernel<<<NB * NN, 256>>>(adj, dis, rsinv);
    convert_adj<<<16384, 256>>>(adj, adjH, adjL);

    // h0 = X @ w_in^T + b_in  -> hcat slice 0 (ld 768)
    dense_gemm<0><<<dim3(2, 128), 256>>>(X, 128, w_in, 128, b_in, hcat, LH, nullptr);

    for (int l = 0; l < 2; l++) {
        const float* Xl = hcat + l * HH;   // ld LH
        convert_x<<<16384, 256>>>(Xl, dis, xlH, xlL, xsH, xsL);
        dim3 ag(2, 8, NB);
        // c0: leaky(A_hat @ Xl)
        adjmma<0><<<ag, 256, SMEM>>>(adjH, adjL, xsH, xsL, nullptr, 0, Xl, LH,
                                     dis, rsinv, nullptr, 0, nullptr, nullptr, hall + 0 * CH);
        // P1 = applyP(Xl); c1 = |Xl - P1|
        adjmma<1><<<ag, 256, SMEM>>>(adjH, adjL, xlH, xlL, Xl, LH, Xl, LH,
                                     dis, rsinv, t0, HH, p0H, p0L, hall + 1 * CH);
        // P2 = applyP(P1); c2 = |P1 - P2|
        adjmma<1><<<ag, 256, SMEM>>>(adjH, adjL, p0H, p0L, t0, HH, t0, HH,
                                     dis, rsinv, t1, HH, p1H, p1L, hall + 2 * CH);
        // P3 = applyP(P2)
        adjmma<2><<<ag, 256, SMEM>>>(adjH, adjL, p1H, p1L, t1, HH, nullptr, 0,
                                     dis, rsinv, t2, HH, p2H, p2L, nullptr);
        // P4 = applyP(P3); c3 = |P2 - P4|
        adjmma<1><<<ag, 256, SMEM>>>(adjH, adjL, p2H, p2L, t2, HH, t1, HH,
                                     dis, rsinv, t0, HH, p0H, p0L, hall + 3 * CH);

        attention_kernel<<<dim3(NN, NB), 256>>>(Xl, LH, hall, ca + l * 2 * HH, hp);

        dense_gemm<1><<<dim3(2, 128), 256>>>(hp, HH, cw1 + (size_t)l * HH * HH, HH,
                                             cb1 + l * HH, ht, HH, nullptr);
        dense_gemm<1><<<dim3(2, 128), 256>>>(ht, HH, cw2 + (size_t)l * HH * HH, HH,
                                             cb2 + l * HH, hcat + (l + 1) * HH, LH, nullptr);
    }

    // mlp1: leaky(hcat @ mlp1_w^T + b)
    dense_gemm<1><<<dim3(2, 128), 256>>>(hcat, LH, m1w, LH, m1b, m1, HH, nullptr);
    // mlp2 + tanh*40 + gumbel -> Z0 (gsinit output)
    dense_gemm<2><<<dim3(8, 128), 256>>>(m1, HH, m2w, HH, m2b, nullptr, 0, Z0);

    // sinkhorn (potentials form)
    zero_uv<<<64, 256>>>(u, v);
    for (int it = 0; it < 20; it++) {
        row_lse<<<NB * NN, 256>>>(Z0, v, u);
        col_lse<<<dim3(16, NB), 256>>>(Z0, u, v);
    }
    row_expsum<<<NB * NN, 256>>>(Z0, u, v, outP, r);
    col_divsum<<<dim3(16, NB), 256>>>(outP, r, c);
    final_scale<<<16384, 256>>>(outP, r, c);
}

// round 6
// speedup vs baseline: 1.5505x; 1.0868x over previous
#include <cuda_runtime.h>
#include <cuda_fp16.h>
#include <cstdint>
#include <math.h>

#define NB 16
#define NN 1024
#define HH 256
#define LH 768          // H*(1+L) = 768

// ---------------- scratch (__device__ globals; no cudaMalloc allowed) ----------------
__device__ float g_hall[(size_t)NB * 4 * NN * HH];   // [b][c][n][h]
__device__ float g_hcat[(size_t)NB * NN * LH];       // [b*n][768]  (h0|h1|h2)
__device__ float g_t0[(size_t)NB * NN * HH];
__device__ float g_t1[(size_t)NB * NN * HH];
__device__ float g_t2[(size_t)NB * NN * HH];
__device__ float g_dis[NB * NN];                     // (rowsum(adj)+1)^-0.5
__device__ float g_rsinv[NB * NN];                   // 1/rowsum(adj)
__device__ float g_u[NB * NN];
__device__ float g_v[NB * NN];
__device__ float g_r[NB * NN];
__device__ float g_c[NB * NN];

// fp16 split operands
__device__ __half g_adjH[(size_t)NB * NN * NN];      // 32MB
__device__ __half g_adjL[(size_t)NB * NN * NN];
__device__ __half g_xlH[(size_t)NB * NN * HH];
__device__ __half g_xlL[(size_t)NB * NN * HH];
__device__ __half g_xsH[(size_t)NB * NN * HH];
__device__ __half g_xsL[(size_t)NB * NN * HH];
__device__ __half g_p0H[(size_t)NB * NN * HH];
__device__ __half g_p0L[(size_t)NB * NN * HH];
__device__ __half g_p1H[(size_t)NB * NN * HH];
__device__ __half g_p1L[(size_t)NB * NN * HH];
__device__ __half g_p2H[(size_t)NB * NN * HH];
__device__ __half g_p2L[(size_t)NB * NN * HH];

// fp16 pairs for dense pipeline
__device__ __half g_wH[720896];                      // packed weights (cw1 l0,l1 | cw2 l0,l1 | m1w | m2w)
__device__ __half g_wL[720896];
__device__ __half g_hpH[(size_t)NB * NN * HH];
__device__ __half g_hpL[(size_t)NB * NN * HH];
__device__ __half g_htH[(size_t)NB * NN * HH];
__device__ __half g_htL[(size_t)NB * NN * HH];
__device__ __half g_m1H[(size_t)NB * NN * HH];
__device__ __half g_m1L[(size_t)NB * NN * HH];
__device__ __half g_hcH[(size_t)NB * NN * LH];
__device__ __half g_hcL[(size_t)NB * NN * LH];

#define BSCALE 256.0f
#define BINV   (1.0f / 256.0f)
#define ACCINV (1.0f / 65536.0f)

// weight pack offsets
#define OW_CW1 0
#define OW_CW2 131072
#define OW_M1W 262144
#define OW_M2W 458752

// ---------------- helpers ----------------
__device__ __forceinline__ float lky(float x) { return x > 0.0f ? x : 0.01f * x; }

__device__ __forceinline__ float warpSum(float v) {
    #pragma unroll
    for (int o = 16; o; o >>= 1) v += __shfl_xor_sync(0xffffffffu, v, o);
    return v;
}
__device__ __forceinline__ float warpMax(float v) {
    #pragma unroll
    for (int o = 16; o; o >>= 1) v = fmaxf(v, __shfl_xor_sync(0xffffffffu, v, o));
    return v;
}

__device__ __forceinline__ uint32_t rotl_(uint32_t v, int s) { return (v << s) | (v >> (32 - s)); }

// Threefry-2x32 with key = (0, 42)  == jax.random.key(42)
__device__ __forceinline__ void threefry_42(uint32_t x0, uint32_t x1, uint32_t& o0, uint32_t& o1) {
    const uint32_t k0 = 0u, k1 = 42u;
    const uint32_t k2 = 0u ^ 42u ^ 0x1BD11BDAu;
    x0 += k0; x1 += k1;
#define TF4(a,b,c,d, ka, kb, inc)                     \
    x0 += x1; x1 = rotl_(x1, a); x1 ^= x0;            \
    x0 += x1; x1 = rotl_(x1, b); x1 ^= x0;            \
    x0 += x1; x1 = rotl_(x1, c); x1 ^= x0;            \
    x0 += x1; x1 = rotl_(x1, d); x1 ^= x0;            \
    x0 += ka; x1 += kb + inc;
    TF4(13, 15, 26, 6,  k1, k2, 1u)
    TF4(17, 29, 16, 24, k2, k0, 2u)
    TF4(13, 15, 26, 6,  k0, k1, 3u)
    TF4(17, 29, 16, 24, k1, k2, 4u)
    TF4(13, 15, 26, 6,  k2, k0, 5u)
#undef TF4
    o0 = x0; o1 = x1;
}

// gumbel noise*0.05, jax_threefry_partitionable layout: counter (0, idx), bits = o0^o1
__device__ __forceinline__ float gumbel_noise(uint32_t idx) {
    uint32_t o0, o1;
    threefry_42(0u, idx, o0, o1);
    uint32_t bits = o0 ^ o1;
    float u = __uint_as_float((bits >> 9) | 0x3f800000u) - 1.0f;
    return -logf(-logf(u + 1e-20f) + 1e-20f) * 0.05f;
}

// ---------------- tensor-core primitives ----------------
__device__ __forceinline__ uint32_t s2u(const void* p) {
    return (uint32_t)__cvta_generic_to_shared(p);
}
__device__ __forceinline__ void cpa16(uint32_t s, const void* g) {
    asm volatile("cp.async.cg.shared.global [%0], [%1], 16;" :: "r"(s), "l"(g));
}
__device__ __forceinline__ void cpa_commit() {
    asm volatile("cp.async.commit_group;" ::: "memory");
}
template<int N>
__device__ __forceinline__ void cpa_wait() {
    asm volatile("cp.async.wait_group %0;" :: "n"(N) : "memory");
}
__device__ __forceinline__ void ldmA4(uint32_t a, uint32_t* r) {
    asm volatile("ldmatrix.sync.aligned.m8n8.x4.shared.b16 {%0,%1,%2,%3}, [%4];"
        : "=r"(r[0]), "=r"(r[1]), "=r"(r[2]), "=r"(r[3]) : "r"(a));
}
__device__ __forceinline__ void ldmB4T(uint32_t a, uint32_t* r) {
    asm volatile("ldmatrix.sync.aligned.m8n8.x4.trans.shared.b16 {%0,%1,%2,%3}, [%4];"
        : "=r"(r[0]), "=r"(r[1]), "=r"(r[2]), "=r"(r[3]) : "r"(a));
}
__device__ __forceinline__ void mma16816(float* d, const uint32_t* A, const uint32_t* b) {
    asm volatile("mma.sync.aligned.m16n8k16.row.col.f32.f16.f16.f32 "
        "{%0,%1,%2,%3},{%4,%5,%6,%7},{%8,%9},{%0,%1,%2,%3};"
        : "+f"(d[0]), "+f"(d[1]), "+f"(d[2]), "+f"(d[3])
        : "r"(A[0]), "r"(A[1]), "r"(A[2]), "r"(A[3]), "r"(b[0]), "r"(b[1]));
}

// ---------------- converters ----------------
__global__ void convert_adj(const float* __restrict__ adj,
                            __half* __restrict__ aH, __half* __restrict__ aL) {
    size_t gid = (size_t)blockIdx.x * 256 + threadIdx.x;   // over 4M float4s
    float4 a = ((const float4*)adj)[gid];
    __half2 h01 = __floats2half2_rn(a.x, a.y);
    __half2 h23 = __floats2half2_rn(a.z, a.w);
    __half2 l01 = __floats2half2_rn(a.x - __low2float(h01), a.y - __high2float(h01));
    __half2 l23 = __floats2half2_rn(a.z - __low2float(h23), a.w - __high2float(h23));
    ((__half2*)aH)[gid * 2]     = h01;
    ((__half2*)aH)[gid * 2 + 1] = h23;
    ((__half2*)aL)[gid * 2]     = l01;
    ((__half2*)aL)[gid * 2 + 1] = l23;
}

// generic fp32 -> (x*256) hi/lo pair
__global__ void convert_pair(const float* __restrict__ src,
                             __half* __restrict__ H, __half* __restrict__ L, int n) {
    int i = blockIdx.x * 256 + threadIdx.x;
    if (i < n) {
        float x = src[i] * BSCALE;
        __half h = __float2half_rn(x);
        H[i] = h;
        L[i] = __float2half_rn(x - __half2float(h));
    }
}

// hcat slice -> xl pair (256*x) and xs pair (256*dis*x)
__global__ void convert_x(const float* __restrict__ Xl, const float* __restrict__ dis,
                          __half* __restrict__ xlH, __half* __restrict__ xlL,
                          __half* __restrict__ xsH, __half* __restrict__ xsL) {
    int gid = blockIdx.x * 256 + threadIdx.x;   // over 16384*256
    int r = gid >> 8, c = gid & 255;
    float x = Xl[(size_t)r * LH + c];
    float xl = x * BSCALE;
    float xs = xl * dis[r];
    __half h1 = __float2half_rn(xl);
    __half h2 = __float2half_rn(xs);
    xlH[gid] = h1; xlL[gid] = __float2half_rn(xl - __half2float(h1));
    xsH[gid] = h2; xsL[gid] = __float2half_rn(xs - __half2float(h2));
}

// ---------------- row sums of adj ----------------
__global__ void rowsum_kernel(const float* __restrict__ adj,
                              float* __restrict__ dis, float* __restrict__ rsinv) {
    int gr = blockIdx.x, t = threadIdx.x;
    float4 a4 = ((const float4*)(adj + ((size_t)gr << 10)))[t];
    float s = a4.x + a4.y + a4.z + a4.w;
    s = warpSum(s);
    __shared__ float sm[8];
    if ((t & 31) == 0) sm[t >> 5] = s;
    __syncthreads();
    if (t == 0) {
        float S = sm[0] + sm[1] + sm[2] + sm[3] + sm[4] + sm[5] + sm[6] + sm[7];
        dis[gr]   = rsqrtf(S + 1.0f);
        rsinv[gr] = 1.0f / S;
    }
}

// ---------------- tensor-core adjacency GEMM: C_b = adj_b @ B_b ----------------
// fp16 two-term split (hi+lo, 3 mma combos), fp32 accumulate. B operands pre-scaled by 256.
template<int MODE>
__global__ void __launch_bounds__(256, 1)
adjmma(const __half* __restrict__ adjH, const __half* __restrict__ adjL,
       const __half* __restrict__ bH, const __half* __restrict__ bL,
       const float* __restrict__ U32, int ldu,
       const float* __restrict__ aux, int ldaux,
       const float* __restrict__ dis, const float* __restrict__ rsinv,
       float* __restrict__ pout, int ldp,
       __half* __restrict__ poutH, __half* __restrict__ poutL,
       float* __restrict__ hallc) {
    extern __shared__ char smx[];
    const uint32_t sbase = s2u(smx);
    const int t = threadIdx.x;
    const int b = blockIdx.z;
    const int m0 = blockIdx.y << 7;
    const int n0 = blockIdx.x << 7;
    const int w = t >> 5, lane = t & 31;
    const int wm = w >> 1, wn = w & 1;
    const int lr16 = lane & 15, lhi = lane >> 4;

    float acc[2][8][4];
    #pragma unroll
    for (int mi = 0; mi < 2; mi++)
        #pragma unroll
        for (int nj = 0; nj < 8; nj++)
            #pragma unroll
            for (int ci = 0; ci < 4; ci++) acc[mi][nj][ci] = 0.0f;

    const int ar = t >> 2,  asg = t & 3;
    const int bk = t >> 4,  bsg = t & 15;

    auto issue = [&](int kt, int st) {
        uint32_t AHb = sbase + st * 37888;
        uint32_t ALb = AHb + 10240;
        uint32_t BHb = ALb + 10240;
        uint32_t BLb = BHb + 8704;
        #pragma unroll
        for (int it = 0; it < 2; it++) {
            int r = ar + (it << 6);
            size_t gA = ((size_t)b << 20) + ((size_t)(m0 + r) << 10) + (kt << 5) + (asg << 3);
            uint32_t sA = (uint32_t)(r * 80 + (asg << 4));
            cpa16(AHb + sA, adjH + gA);
            cpa16(ALb + sA, adjL + gA);
            int k = bk + (it << 4);
            size_t gB = ((size_t)((b << 10) + (kt << 5) + k) << 8) + n0 + (bsg << 3);
            uint32_t sB = (uint32_t)(k * 272 + (bsg << 4));
            cpa16(BHb + sB, bH + gB);
            cpa16(BLb + sB, bL + gB);
        }
        cpa_commit();
    };

    issue(0, 0);
    for (int kt = 0; kt < 32; kt++) {
        if (kt < 31) { issue(kt + 1, (kt + 1) & 1); cpa_wait<1>(); }
        else         { cpa_wait<0>(); }
        __syncthreads();

        int st = kt & 1;
        uint32_t AHb = sbase + st * 37888;
        uint32_t ALb = AHb + 10240;
        uint32_t BHb = ALb + 10240;
        uint32_t BLb = BHb + 8704;

        #pragma unroll
        for (int kk = 0; kk < 32; kk += 16) {
            uint32_t aH[2][4], aL[2][4];
            uint32_t cc2 = (uint32_t)((kk + (lhi << 3)) << 1);
            #pragma unroll
            for (int mi = 0; mi < 2; mi++) {
                uint32_t ro = (uint32_t)((wm * 32 + mi * 16 + lr16) * 80);
                ldmA4(AHb + ro + cc2, aH[mi]);
                ldmA4(ALb + ro + cc2, aL[mi]);
            }
            uint32_t bHf[8][2], bLf[8][2];
            #pragma unroll
            for (int np = 0; np < 4; np++) {
                uint32_t ko = (uint32_t)((kk + lr16) * 272);
                uint32_t nc = (uint32_t)((wn * 64 + np * 16 + (lhi << 3)) << 1);
                uint32_t r4[4];
                ldmB4T(BHb + ko + nc, r4);
                bHf[np*2][0] = r4[0]; bHf[np*2][1] = r4[1];
                bHf[np*2+1][0] = r4[2]; bHf[np*2+1][1] = r4[3];
                ldmB4T(BLb + ko + nc, r4);
                bLf[np*2][0] = r4[0]; bLf[np*2][1] = r4[1];
                bLf[np*2+1][0] = r4[2]; bLf[np*2+1][1] = r4[3];
            }
            #pragma unroll
            for (int mi = 0; mi < 2; mi++)
                #pragma unroll
                for (int nj = 0; nj < 8; nj++) {
                    mma16816(acc[mi][nj], aH[mi], bHf[nj]);
                    mma16816(acc[mi][nj], aH[mi], bLf[nj]);
                    mma16816(acc[mi][nj], aL[mi], bHf[nj]);
                }
        }
        __syncthreads();
    }

    const int g8 = lane >> 2, t4 = lane & 3;
    #pragma unroll
    for (int mi = 0; mi < 2; mi++)
        #pragma unroll
        for (int nj = 0; nj < 8; nj++)
            #pragma unroll
            for (int ci = 0; ci < 4; ci++) {
                int il = m0 + wm * 32 + mi * 16 + g8 + ((ci >> 1) << 3);
                int cg = n0 + wn * 64 + nj * 8 + (t4 << 1) + (ci & 1);
                int gi = (b << 10) + il;
                float a = acc[mi][nj][ci] * BINV;
                size_t hix = ((size_t)b << 20) + ((size_t)il << 8) + cg;
                if (MODE == 0) {
                    float di = dis[gi];
                    float xv = aux[(size_t)gi * ldaux + cg];
                    hallc[hix] = lky(di * a + di * di * xv);
                } else {
                    float p = 0.5f * (U32[(size_t)gi * ldu + cg] + rsinv[gi] * a);
                    pout[(size_t)gi * ldp + cg] = p;
                    float ps = p * BSCALE;
                    __half ph = __float2half_rn(ps);
                    size_t pix = ((size_t)gi << 8) + cg;
                    poutH[pix] = ph;
                    poutL[pix] = __float2half_rn(ps - __half2float(ph));
                    if (MODE == 1) {
                        float ax = aux[(size_t)gi * ldaux + cg];
                        hallc[hix] = fabsf(ax - p);
                    }
                }
            }
}

// ---------------- dense HMMA GEMM: C[16384, Nout] = ep(A @ W^T + b) ----------------
// A fp16 pair [16384,K] (K-major), W fp16 pair [Nout,K] (K-major), both pre-scaled x256.
// EP 1: leaky -> optional fp32 out + optional fp16 pair out
// EP 2: Z0 epilogue (tanh*40 + gumbel)/tau -> zbuf
template<int EP>
__global__ void __launch_bounds__(256, 1)
hgemm(const __half* __restrict__ AH, const __half* __restrict__ AL, int lda,
      const __half* __restrict__ WH, const __half* __restrict__ WL, int K,
      const float* __restrict__ bias,
      float* __restrict__ out, int ldo,
      __half* __restrict__ poH, __half* __restrict__ poL, int ldp,
      float* __restrict__ zbuf) {
    extern __shared__ char smx[];
    const uint32_t sbase = s2u(smx);
    const int t = threadIdx.x;
    const int m0 = blockIdx.y << 7;
    const int n0 = blockIdx.x << 7;
    const int w = t >> 5, lane = t & 31;
    const int wm = w >> 1, wn = w & 1;
    const int lr16 = lane & 15, lhi = lane >> 4;

    float acc[2][8][4];
    #pragma unroll
    for (int mi = 0; mi < 2; mi++)
        #pragma unroll
        for (int nj = 0; nj < 8; nj++)
            #pragma unroll
            for (int ci = 0; ci < 4; ci++) acc[mi][nj][ci] = 0.0f;

    const int lrow = t >> 1, lsg = t & 1;   // loader: row 0..127, 32B-half

    // stage layout: AH(10240) AL(10240) WH(10240) WL(10240) = 40960/stage
    auto issue = [&](int kt, int st) {
        uint32_t AHb = sbase + st * 40960;
        uint32_t ALb = AHb + 10240;
        uint32_t WHb = ALb + 10240;
        uint32_t WLb = WHb + 10240;
        uint32_t so = (uint32_t)(lrow * 80 + (lsg << 5));
        size_t gA = (size_t)(m0 + lrow) * lda + (kt << 5) + (lsg << 4);
        size_t gW = (size_t)(n0 + lrow) * K   + (kt << 5) + (lsg << 4);
        cpa16(AHb + so,      AH + gA);
        cpa16(AHb + so + 16, AH + gA + 8);
        cpa16(ALb + so,      AL + gA);
        cpa16(ALb + so + 16, AL + gA + 8);
        cpa16(WHb + so,      WH + gW);
        cpa16(WHb + so + 16, WH + gW + 8);
        cpa16(WLb + so,      WL + gW);
        cpa16(WLb + so + 16, WL + gW + 8);
        cpa_commit();
    };

    const int nchunks = K >> 5;
    issue(0, 0);
    for (int kt = 0; kt < nchunks; kt++) {
        if (kt < nchunks - 1) { issue(kt + 1, (kt + 1) & 1); cpa_wait<1>(); }
        else                  { cpa_wait<0>(); }
        __syncthreads();

        int st = kt & 1;
        uint32_t AHb = sbase + st * 40960;
        uint32_t ALb = AHb + 10240;
        uint32_t WHb = ALb + 10240;
        uint32_t WLb = WHb + 10240;

        #pragma unroll
        for (int kk = 0; kk < 32; kk += 16) {
            uint32_t aH[2][4], aL[2][4];
            uint32_t cc2 = (uint32_t)((kk + (lhi << 3)) << 1);
            #pragma unroll
            for (int mi = 0; mi < 2; mi++) {
                uint32_t ro = (uint32_t)((wm * 32 + mi * 16 + lr16) * 80);
                ldmA4(AHb + ro + cc2, aH[mi]);
                ldmA4(ALb + ro + cc2, aL[mi]);
            }
            // B frags via non-trans ldmatrix on [n][k] rows
            uint32_t bHf[8][2], bLf[8][2];
            uint32_t nrow = (uint32_t)(((lane >> 4) << 3) + (lane & 7));   // 0..15 within 16-group
            uint32_t kb   = (uint32_t)(kk * 2 + ((lane >> 3) & 1) * 16);
            #pragma unroll
            for (int np = 0; np < 4; np++) {
                uint32_t ad = (uint32_t)((wn * 64 + np * 16 + nrow) * 80) + kb;
                uint32_t r4[4];
                ldmA4(WHb + ad, r4);   // non-trans
                bHf[np*2][0] = r4[0]; bHf[np*2][1] = r4[1];
                bHf[np*2+1][0] = r4[2]; bHf[np*2+1][1] = r4[3];
                ldmA4(WLb + ad, r4);
                bLf[np*2][0] = r4[0]; bLf[np*2][1] = r4[1];
                bLf[np*2+1][0] = r4[2]; bLf[np*2+1][1] = r4[3];
            }
            #pragma unroll
            for (int mi = 0; mi < 2; mi++)
                #pragma unroll
                for (int nj = 0; nj < 8; nj++) {
                    mma16816(acc[mi][nj], aH[mi], bHf[nj]);
                    mma16816(acc[mi][nj], aH[mi], bLf[nj]);
                    mma16816(acc[mi][nj], aL[mi], bHf[nj]);
                }
        }
        __syncthreads();
    }

    const int g8 = lane >> 2, t4 = lane & 3;
    #pragma unroll
    for (int mi = 0; mi < 2; mi++)
        #pragma unroll
        for (int nj = 0; nj < 8; nj++)
            #pragma unroll
            for (int ci = 0; ci < 4; ci++) {
                int rg = m0 + wm * 32 + mi * 16 + g8 + ((ci >> 1) << 3);
                int cg = n0 + wn * 64 + nj * 8 + (t4 << 1) + (ci & 1);
                float v = acc[mi][nj][ci] * ACCINV + __ldg(&bias[cg]);
                if (EP == 1) {
                    float o = lky(v);
                    if (out) out[(size_t)rg * ldo + cg] = o;
                    if (poH) {
                        float ps = o * BSCALE;
                        __half ph = __float2half_rn(ps);
                        size_t pix = (size_t)rg * ldp + cg;
                        poH[pix] = ph;
                        poL[pix] = __float2half_rn(ps - __half2float(ph));
                    }
                } else {
                    uint32_t idx = ((uint32_t)rg << 10) + (uint32_t)cg;
                    float z = (tanhf(v) * 40.0f + gumbel_noise(idx)) * 10.0f;
                    zbuf[idx] = z;
                }
            }
}

// ---------------- dense GEMM (FFMA, used only for w_in): C = X @ W^T + b ----------------
__global__ void __launch_bounds__(256)
dense_gemm(const float* __restrict__ X, int ldx,
           const float* __restrict__ W, int K,
           const float* __restrict__ bias,
           float* __restrict__ out, int ldo) {
    __shared__ float As[16][132];
    __shared__ float Bs[16][132];
    const int t  = threadIdx.x;
    const int m0 = blockIdx.y << 7;
    const int n0 = blockIdx.x << 7;
    const int tx = t & 15, ty = t >> 4;
    const int lr = t >> 1;
    const int lk = (t & 1) << 3;

    float acc[8][8];
    #pragma unroll
    for (int i = 0; i < 8; i++)
        #pragma unroll
        for (int j = 0; j < 8; j++) acc[i][j] = 0.0f;

    const float* Ap = X + (size_t)(m0 + lr) * ldx + lk;
    const float* Bp = W + (size_t)(n0 + lr) * K + lk;

    for (int kt = 0; kt < K; kt += 16) {
        float4 av0 = *(const float4*)(Ap + kt);
        float4 av1 = *(const float4*)(Ap + kt + 4);
        float4 bv0 = *(const float4*)(Bp + kt);
        float4 bv1 = *(const float4*)(Bp + kt + 4);
        As[lk+0][lr]=av0.x; As[lk+1][lr]=av0.y; As[lk+2][lr]=av0.z; As[lk+3][lr]=av0.w;
        As[lk+4][lr]=av1.x; As[lk+5][lr]=av1.y; As[lk+6][lr]=av1.z; As[lk+7][lr]=av1.w;
        Bs[lk+0][lr]=bv0.x; Bs[lk+1][lr]=bv0.y; Bs[lk+2][lr]=bv0.z; Bs[lk+3][lr]=bv0.w;
        Bs[lk+4][lr]=bv1.x; Bs[lk+5][lr]=bv1.y; Bs[lk+6][lr]=bv1.z; Bs[lk+7][lr]=bv1.w;
        __syncthreads();
        #pragma unroll
        for (int k = 0; k < 16; k++) {
            float af[8], bf[8];
            *(float4*)(af)     = *(const float4*)&As[k][(ty<<3)];
            *(float4*)(af + 4) = *(const float4*)&As[k][(ty<<3) + 4];
            *(float4*)(bf)     = *(const float4*)&Bs[k][(tx<<3)];
            *(float4*)(bf + 4) = *(const float4*)&Bs[k][(tx<<3) + 4];
            #pragma unroll
            for (int i = 0; i < 8; i++)
                #pragma unroll
                for (int j = 0; j < 8; j++)
                    acc[i][j] = fmaf(af[i], bf[j], acc[i][j]);
        }
        __syncthreads();
    }

    #pragma unroll
    for (int i = 0; i < 8; i++) {
        int rg = m0 + (ty << 3) + i;
        #pragma unroll
        for (int j = 0; j < 8; j++) {
            int cg = n0 + (tx << 3) + j;
            out[(size_t)rg * ldo + cg] = acc[i][j] + __ldg(&bias[cg]);
        }
    }
}

// ---------------- attention + channel mix -> hp fp16 pair ----------------
__global__ void attention_kernel(const float* __restrict__ Xl, int ldx,
                                 const float* __restrict__ hall,
                                 const float* __restrict__ a,
                                 __half* __restrict__ hpH, __half* __restrict__ hpL) {
    int n = blockIdx.x, b = blockIdx.y, t = threadIdx.x;
    float xv = Xl[(size_t)((b << 10) + n) * ldx + t];
    float hv[4];
    size_t hbase = ((size_t)b << 20) + ((size_t)n << 8) + t;
    #pragma unroll
    for (int c = 0; c < 4; c++) hv[c] = hall[hbase + ((size_t)c << 18)];
    float a1 = a[t], a2 = a[256 + t];
    float p[5];
    p[0] = fmaxf(xv, 0.0f) * a1;
    #pragma unroll
    for (int c = 0; c < 4; c++) p[1 + c] = fmaxf(hv[c], 0.0f) * a2;

    __shared__ float sm[5][8];
    #pragma unroll
    for (int q = 0; q < 5; q++) {
        float s = warpSum(p[q]);
        if ((t & 31) == 0) sm[q][t >> 5] = s;
    }
    __syncthreads();
    float S[5];
    #pragma unroll
    for (int q = 0; q < 5; q++) {
        float s = sm[q][0];
        #pragma unroll
        for (int w = 1; w < 8; w++) s += sm[q][w];
        S[q] = s;
    }
    float e0 = S[0] + S[1], e1 = S[0] + S[2], e2 = S[0] + S[3], e3 = S[0] + S[4];
    float M = fmaxf(fmaxf(e0, e1), fmaxf(e2, e3));
    float w0 = __expf(e0 - M), w1 = __expf(e1 - M), w2 = __expf(e2 - M), w3 = __expf(e3 - M);
    float ws = w0 + w1 + w2 + w3;
    float o = w0 * hv[0] + w1 * hv[1] + w2 * hv[2] + w3 * hv[3];
    float hpv = 0.25f * o / ws;
    float ps = hpv * BSCALE;
    __half ph = __float2half_rn(ps);
    size_t pix = (size_t)((b << 10) + n) * HH + t;
    hpH[pix] = ph;
    hpL[pix] = __float2half_rn(ps - __half2float(ph));
}

// ---------------- sinkhorn ----------------
__global__ void zero_uv(float* __restrict__ u, float* __restrict__ v) {
    int i = blockIdx.x * blockDim.x + threadIdx.x;
    if (i < NB * NN) { u[i] = 0.0f; v[i] = 0.0f; }
}

__global__ void row_lse(const float* __restrict__ Z0, const float* __restrict__ v,
                        float* __restrict__ u) {
    int gr = blockIdx.x, b = gr >> 10, t = threadIdx.x;
    float4 z4 = ((const float4*)(Z0 + ((size_t)gr << 10)))[t];
    float4 v4 = ((const float4*)(v + (b << 10)))[t];
    float a0 = z4.x - v4.x, a1 = z4.y - v4.y, a2 = z4.z - v4.z, a3 = z4.w - v4.w;
    float m = fmaxf(fmaxf(a0, a1), fmaxf(a2, a3));
    __shared__ float sm[8];
    m = warpMax(m);
    if ((t & 31) == 0) sm[t >> 5] = m;
    __syncthreads();
    float M = sm[0];
    #pragma unroll
    for (int i = 1; i < 8; i++) M = fmaxf(M, sm[i]);
    __syncthreads();
    float s = __expf(a0 - M) + __expf(a1 - M) + __expf(a2 - M) + __expf(a3 - M);
    s = warpSum(s);
    if ((t & 31) == 0) sm[t >> 5] = s;
    __syncthreads();
    if (t == 0) {
        float S = sm[0] + sm[1] + sm[2] + sm[3] + sm[4] + sm[5] + sm[6] + sm[7];
        u[gr] = M + __logf(S);
    }
}

__global__ void col_lse(const float* __restrict__ Z0, const float* __restrict__ u,
                        float* __restrict__ v) {
    int b = blockIdx.y, t = threadIdx.x;
    int jj = t & 63, seg = t >> 6;
    int j = (blockIdx.x << 6) + jj;
    __shared__ float us[1024];
    __shared__ float red[256];
    for (int i = t; i < 1024; i += 256) us[i] = u[(b << 10) + i];
    __syncthreads();
    const float* zb = Z0 + ((size_t)b << 20);
    float m = -INFINITY;
    int i0 = seg << 8;
    for (int i = i0; i < i0 + 256; i++)
        m = fmaxf(m, zb[((size_t)i << 10) + j] - us[i]);
    red[t] = m;
    __syncthreads();
    float M = fmaxf(fmaxf(red[jj], red[jj + 64]), fmaxf(red[jj + 128], red[jj + 192]));
    __syncthreads();
    float s = 0.0f;
    for (int i = i0; i < i0 + 256; i++)
        s += __expf(zb[((size_t)i << 10) + j] - us[i] - M);
    red[t] = s;
    __syncthreads();
    if (seg == 0) {
        float S = red[jj] + red[jj + 64] + red[jj + 128] + red[jj + 192];
        v[(b << 10) + j] = M + __logf(S);
    }
}

__global__ void row_expsum(const float* __restrict__ Z0, const float* __restrict__ u,
                           const float* __restrict__ v, float* __restrict__ P,
                           float* __restrict__ r) {
    int gr = blockIdx.x, b = gr >> 10, t = threadIdx.x;
    float uu = u[gr];
    float4 z4 = ((const float4*)(Z0 + ((size_t)gr << 10)))[t];
    float4 v4 = ((const float4*)(v + (b << 10)))[t];
    float4 e;
    e.x = __expf(z4.x - uu - v4.x);
    e.y = __expf(z4.y - uu - v4.y);
    e.z = __expf(z4.z - uu - v4.z);
    e.w = __expf(z4.w - uu - v4.w);
    ((float4*)(P + ((size_t)gr << 10)))[t] = e;
    float s = e.x + e.y + e.z + e.w;
    s = warpSum(s);
    __shared__ float sm[8];
    if ((t & 31) == 0) sm[t >> 5] = s;
    __syncthreads();
    if (t == 0)
        r[gr] = sm[0] + sm[1] + sm[2] + sm[3] + sm[4] + sm[5] + sm[6] + sm[7];
}

__global__ void col_divsum(const float* __restrict__ P, const float* __restrict__ r,
                           float* __restrict__ c) {
    int b = blockIdx.y, t = threadIdx.x;
    int jj = t & 63, seg = t >> 6;
    int j = (blockIdx.x << 6) + jj;
    __shared__ float ri[1024];
    __shared__ float red[256];
    for (int i = t; i < 1024; i += 256) ri[i] = 1.0f / r[(b << 10) + i];
    __syncthreads();
    const float* pb = P + ((size_t)b << 20);
    float s = 0.0f;
    int i0 = seg << 8;
    for (int i = i0; i < i0 + 256; i++)
        s += pb[((size_t)i << 10) + j] * ri[i];
    red[t] = s;
    __syncthreads();
    if (seg == 0)
        c[(b << 10) + j] = red[jj] + red[jj + 64] + red[jj + 128] + red[jj + 192];
}

__global__ void final_scale(float* __restrict__ P, const float* __restrict__ r,
                            const float* __restrict__ c) {
    size_t q = (size_t)blockIdx.x * blockDim.x + threadIdx.x;
    size_t flat = q << 2;
    int gr = (int)(flat >> 10);
    int b  = gr >> 10;
    int j  = (int)(flat & 1023);
    float rin = 1.0f / r[gr];
    float4 cc = *(const float4*)(c + (b << 10) + j);
    float4 p = ((float4*)P)[q];
    p.x = p.x * rin / cc.x;
    p.y = p.y * rin / cc.y;
    p.z = p.z * rin / cc.z;
    p.w = p.w * rin / cc.w;
    ((float4*)P)[q] = p;
}

// ---------------- launch ----------------
extern "C" void kernel_launch(void* const* d_in, const int* in_sizes, int n_in,
                              void* d_out, int out_size) {
    (void)in_sizes; (void)n_in; (void)out_size;
    const float* X    = (const float*)d_in[0];
    const float* adj  = (const float*)d_in[1];
    const float* w_in = (const float*)d_in[2];
    const float* b_in = (const float*)d_in[3];
    const float* cw1  = (const float*)d_in[4];
    const float* cb1  = (const float*)d_in[5];
    const float* cw2  = (const float*)d_in[6];
    const float* cb2  = (const float*)d_in[7];
    const float* ca   = (const float*)d_in[8];
    const float* m1w  = (const float*)d_in[9];
    const float* m1b  = (const float*)d_in[10];
    const float* m2w  = (const float*)d_in[11];
    const float* m2b  = (const float*)d_in[12];

    float* outP = (float*)d_out;
    float* Z0   = outP + (size_t)NB * NN * NN;

    float *hall, *hcat, *t0, *t1, *t2, *dis, *rsinv, *u, *v, *r, *c;
    __half *adjH, *adjL, *xlH, *xlL, *xsH, *xsL, *p0H, *p0L, *p1H, *p1L, *p2H, *p2L;
    __half *wH, *wL, *hpH, *hpL, *htH, *htL, *m1H, *m1L, *hcH, *hcL;
    cudaGetSymbolAddress((void**)&hall, g_hall);
    cudaGetSymbolAddress((void**)&hcat, g_hcat);
    cudaGetSymbolAddress((void**)&t0, g_t0);
    cudaGetSymbolAddress((void**)&t1, g_t1);
    cudaGetSymbolAddress((void**)&t2, g_t2);
    cudaGetSymbolAddress((void**)&dis, g_dis);
    cudaGetSymbolAddress((void**)&rsinv, g_rsinv);
    cudaGetSymbolAddress((void**)&u, g_u);
    cudaGetSymbolAddress((void**)&v, g_v);
    cudaGetSymbolAddress((void**)&r, g_r);
    cudaGetSymbolAddress((void**)&c, g_c);
    cudaGetSymbolAddress((void**)&adjH, g_adjH);
    cudaGetSymbolAddress((void**)&adjL, g_adjL);
    cudaGetSymbolAddress((void**)&xlH, g_xlH);
    cudaGetSymbolAddress((void**)&xlL, g_xlL);
    cudaGetSymbolAddress((void**)&xsH, g_xsH);
    cudaGetSymbolAddress((void**)&xsL, g_xsL);
    cudaGetSymbolAddress((void**)&p0H, g_p0H);
    cudaGetSymbolAddress((void**)&p0L, g_p0L);
    cudaGetSymbolAddress((void**)&p1H, g_p1H);
    cudaGetSymbolAddress((void**)&p1L, g_p1L);
    cudaGetSymbolAddress((void**)&p2H, g_p2H);
    cudaGetSymbolAddress((void**)&p2L, g_p2L);
    cudaGetSymbolAddress((void**)&wH, g_wH);
    cudaGetSymbolAddress((void**)&wL, g_wL);
    cudaGetSymbolAddress((void**)&hpH, g_hpH);
    cudaGetSymbolAddress((void**)&hpL, g_hpL);
    cudaGetSymbolAddress((void**)&htH, g_htH);
    cudaGetSymbolAddress((void**)&htL, g_htL);
    cudaGetSymbolAddress((void**)&m1H, g_m1H);
    cudaGetSymbolAddress((void**)&m1L, g_m1L);
    cudaGetSymbolAddress((void**)&hcH, g_hcH);
    cudaGetSymbolAddress((void**)&hcL, g_hcL);

    const int SMEM_A = 75776;   // adjmma
    const int SMEM_H = 81920;   // hgemm
    cudaFuncSetAttribute(adjmma<0>, cudaFuncAttributeMaxDynamicSharedMemorySize, SMEM_A);
    cudaFuncSetAttribute(adjmma<1>, cudaFuncAttributeMaxDynamicSharedMemorySize, SMEM_A);
    cudaFuncSetAttribute(adjmma<2>, cudaFuncAttributeMaxDynamicSharedMemorySize, SMEM_A);
    cudaFuncSetAttribute(hgemm<1>, cudaFuncAttributeMaxDynamicSharedMemorySize, SMEM_H);
    cudaFuncSetAttribute(hgemm<2>, cudaFuncAttributeMaxDynamicSharedMemorySize, SMEM_H);

    const size_t CH = (size_t)NN * HH;  // hall channel stride

    rowsum_kernel<<<NB * NN, 256>>>(adj, dis, rsinv);
    convert_adj<<<16384, 256>>>(adj, adjH, adjL);

    // weight pairs
    convert_pair<<<256, 256>>>(cw1,          wH + OW_CW1,          wL + OW_CW1,          65536);
    convert_pair<<<256, 256>>>(cw1 + 65536,  wH + OW_CW1 + 65536,  wL + OW_CW1 + 65536,  65536);
    convert_pair<<<256, 256>>>(cw2,          wH + OW_CW2,          wL + OW_CW2,          65536);
    convert_pair<<<256, 256>>>(cw2 + 65536,  wH + OW_CW2 + 65536,  wL + OW_CW2 + 65536,  65536);
    convert_pair<<<768, 256>>>(m1w,          wH + OW_M1W,          wL + OW_M1W,          196608);
    convert_pair<<<1024, 256>>>(m2w,         wH + OW_M2W,          wL + OW_M2W,          262144);

    // h0 = X @ w_in^T + b_in  -> hcat slice 0 (ld 768), FFMA (small)
    dense_gemm<<<dim3(2, 128), 256>>>(X, 128, w_in, 128, b_in, hcat, LH);

    for (int l = 0; l < 2; l++) {
        const float* Xl = hcat + l * HH;   // ld LH
        convert_x<<<16384, 256>>>(Xl, dis, xlH, xlL, xsH, xsL);
        dim3 ag(2, 8, NB);
        adjmma<0><<<ag, 256, SMEM_A>>>(adjH, adjL, xsH, xsL, nullptr, 0, Xl, LH,
                                       dis, rsinv, nullptr, 0, nullptr, nullptr, hall + 0 * CH);
        adjmma<1><<<ag, 256, SMEM_A>>>(adjH, adjL, xlH, xlL, Xl, LH, Xl, LH,
                                       dis, rsinv, t0, HH, p0H, p0L, hall + 1 * CH);
        adjmma<1><<<ag, 256, SMEM_A>>>(adjH, adjL, p0H, p0L, t0, HH, t0, HH,
                                       dis, rsinv, t1, HH, p1H, p1L, hall + 2 * CH);
        adjmma<2><<<ag, 256, SMEM_A>>>(adjH, adjL, p1H, p1L, t1, HH, nullptr, 0,
                                       dis, rsinv, t2, HH, p2H, p2L, nullptr);
        adjmma<1><<<ag, 256, SMEM_A>>>(adjH, adjL, p2H, p2L, t2, HH, t1, HH,
                                       dis, rsinv, t0, HH, p0H, p0L, hall + 3 * CH);

        attention_kernel<<<dim3(NN, NB), 256>>>(Xl, LH, hall, ca + l * 2 * HH, hpH, hpL);

        // conv1: leaky(hp @ w1^T + b1) -> ht pair
        hgemm<1><<<dim3(2, 128), 256, SMEM_H>>>(hpH, hpL, HH,
            wH + OW_CW1 + l * 65536, wL + OW_CW1 + l * 65536, HH, cb1 + l * HH,
            nullptr, 0, htH, htL, HH, nullptr);
        // conv2: leaky(ht @ w2^T + b2) -> hcat slice (fp32)
        hgemm<1><<<dim3(2, 128), 256, SMEM_H>>>(htH, htL, HH,
            wH + OW_CW2 + l * 65536, wL + OW_CW2 + l * 65536, HH, cb2 + l * HH,
            hcat + (l + 1) * HH, LH, nullptr, nullptr, 0, nullptr);
    }

    // hcat -> pair, then mlp1 -> m1 pair
    convert_pair<<<49152, 256>>>(hcat, hcH, hcL, 16384 * LH);
    hgemm<1><<<dim3(2, 128), 256, SMEM_H>>>(hcH, hcL, LH,
        wH + OW_M1W, wL + OW_M1W, LH, m1b,
        nullptr, 0, m1H, m1L, HH, nullptr);
    // mlp2 + tanh*40 + gumbel -> Z0
    hgemm<2><<<dim3(8, 128), 256, SMEM_H>>>(m1H, m1L, HH,
        wH + OW_M2W, wL + OW_M2W, HH, m2b,
        nullptr, 0, nullptr, nullptr, 0, Z0);

    // sinkhorn (potentials form)
    zero_uv<<<64, 256>>>(u, v);
    for (int it = 0; it < 20; it++) {
        row_lse<<<NB * NN, 256>>>(Z0, v, u);
        col_lse<<<dim3(16, NB), 256>>>(Z0, u, v);
    }
    row_expsum<<<NB * NN, 256>>>(Z0, u, v, outP, r);
    col_divsum<<<dim3(16, NB), 256>>>(outP, r, c);
    final_scale<<<16384, 256>>>(outP, r, c);
}

// round 7
// speedup vs baseline: 1.7310x; 1.1164x over previous
#include <cuda_runtime.h>
#include <cuda_fp16.h>
#include <cstdint>
#include <math.h>

#define NB 16
#define NN 1024
#define HH 256
#define LH 768          // H*(1+L) = 768
#define NBLK 256        // sinkhorn persistent grid

// ---------------- scratch (__device__ globals; no cudaMalloc allowed) ----------------
__device__ float g_hall[(size_t)NB * 4 * NN * HH];   // [b][c][n][h]
__device__ float g_hcat[(size_t)NB * NN * LH];       // [b*n][768]  (h0|h1|h2)
__device__ float g_t0[(size_t)NB * NN * HH];
__device__ float g_t1[(size_t)NB * NN * HH];
__device__ float g_t2[(size_t)NB * NN * HH];
__device__ float g_dis[NB * NN];
__device__ float g_rsinv[NB * NN];
__device__ float g_u[NB * NN];
__device__ float g_v[NB * NN];
__device__ float g_r[NB * NN];
__device__ float g_c[NB * NN];

// fp16 split operands
__device__ __half g_adjH[(size_t)NB * NN * NN];
__device__ __half g_adjL[(size_t)NB * NN * NN];
__device__ __half g_xlH[(size_t)NB * NN * HH];
__device__ __half g_xlL[(size_t)NB * NN * HH];
__device__ __half g_xsH[(size_t)NB * NN * HH];
__device__ __half g_xsL[(size_t)NB * NN * HH];
__device__ __half g_p0H[(size_t)NB * NN * HH];
__device__ __half g_p0L[(size_t)NB * NN * HH];
__device__ __half g_p1H[(size_t)NB * NN * HH];
__device__ __half g_p1L[(size_t)NB * NN * HH];
__device__ __half g_p2H[(size_t)NB * NN * HH];
__device__ __half g_p2L[(size_t)NB * NN * HH];

// fp16 pairs for dense pipeline
__device__ __half g_wH[720896];
__device__ __half g_wL[720896];
__device__ __half g_hpH[(size_t)NB * NN * HH];
__device__ __half g_hpL[(size_t)NB * NN * HH];
__device__ __half g_htH[(size_t)NB * NN * HH];
__device__ __half g_htL[(size_t)NB * NN * HH];
__device__ __half g_m1H[(size_t)NB * NN * HH];
__device__ __half g_m1L[(size_t)NB * NN * HH];
__device__ __half g_hcH[(size_t)NB * NN * LH];
__device__ __half g_hcL[(size_t)NB * NN * LH];

// grid barrier state
__device__ unsigned g_barcnt = 0;
__device__ unsigned g_bargen = 0;

#define BSCALE 256.0f
#define BINV   (1.0f / 256.0f)
#define ACCINV (1.0f / 65536.0f)

// weight pack offsets
#define OW_CW1 0
#define OW_CW2 131072
#define OW_M1W 262144
#define OW_M2W 458752

// ---------------- helpers ----------------
__device__ __forceinline__ float lky(float x) { return x > 0.0f ? x : 0.01f * x; }

__device__ __forceinline__ float warpSum(float v) {
    #pragma unroll
    for (int o = 16; o; o >>= 1) v += __shfl_xor_sync(0xffffffffu, v, o);
    return v;
}
__device__ __forceinline__ float warpMax(float v) {
    #pragma unroll
    for (int o = 16; o; o >>= 1) v = fmaxf(v, __shfl_xor_sync(0xffffffffu, v, o));
    return v;
}

__device__ __forceinline__ uint32_t rotl_(uint32_t v, int s) { return (v << s) | (v >> (32 - s)); }

// Threefry-2x32 with key = (0, 42)
__device__ __forceinline__ void threefry_42(uint32_t x0, uint32_t x1, uint32_t& o0, uint32_t& o1) {
    const uint32_t k0 = 0u, k1 = 42u;
    const uint32_t k2 = 0u ^ 42u ^ 0x1BD11BDAu;
    x0 += k0; x1 += k1;
#define TF4(a,b,c,d, ka, kb, inc)                     \
    x0 += x1; x1 = rotl_(x1, a); x1 ^= x0;            \
    x0 += x1; x1 = rotl_(x1, b); x1 ^= x0;            \
    x0 += x1; x1 = rotl_(x1, c); x1 ^= x0;            \
    x0 += x1; x1 = rotl_(x1, d); x1 ^= x0;            \
    x0 += ka; x1 += kb + inc;
    TF4(13, 15, 26, 6,  k1, k2, 1u)
    TF4(17, 29, 16, 24, k2, k0, 2u)
    TF4(13, 15, 26, 6,  k0, k1, 3u)
    TF4(17, 29, 16, 24, k1, k2, 4u)
    TF4(13, 15, 26, 6,  k2, k0, 5u)
#undef TF4
    o0 = x0; o1 = x1;
}

__device__ __forceinline__ float gumbel_noise(uint32_t idx) {
    uint32_t o0, o1;
    threefry_42(0u, idx, o0, o1);
    uint32_t bits = o0 ^ o1;
    float u = __uint_as_float((bits >> 9) | 0x3f800000u) - 1.0f;
    return -logf(-logf(u + 1e-20f) + 1e-20f) * 0.05f;
}

// ---------------- grid barrier (all NBLK blocks resident) ----------------
__device__ __forceinline__ void gridbar(unsigned& gen) {
    __syncthreads();
    if (threadIdx.x == 0) {
        __threadfence();
        if (atomicInc(&g_barcnt, NBLK - 1) == NBLK - 1) {
            atomicExch(&g_bargen, gen + 1);
        } else {
            while (*(volatile unsigned*)&g_bargen == gen) { }
        }
        __threadfence();
    }
    __syncthreads();
    gen++;
}

// ---------------- tensor-core primitives ----------------
__device__ __forceinline__ uint32_t s2u(const void* p) {
    return (uint32_t)__cvta_generic_to_shared(p);
}
__device__ __forceinline__ void cpa16(uint32_t s, const void* g) {
    asm volatile("cp.async.cg.shared.global [%0], [%1], 16;" :: "r"(s), "l"(g));
}
__device__ __forceinline__ void cpa_commit() {
    asm volatile("cp.async.commit_group;" ::: "memory");
}
template<int N>
__device__ __forceinline__ void cpa_wait() {
    asm volatile("cp.async.wait_group %0;" :: "n"(N) : "memory");
}
__device__ __forceinline__ void ldmA4(uint32_t a, uint32_t* r) {
    asm volatile("ldmatrix.sync.aligned.m8n8.x4.shared.b16 {%0,%1,%2,%3}, [%4];"
        : "=r"(r[0]), "=r"(r[1]), "=r"(r[2]), "=r"(r[3]) : "r"(a));
}
__device__ __forceinline__ void ldmB4T(uint32_t a, uint32_t* r) {
    asm volatile("ldmatrix.sync.aligned.m8n8.x4.trans.shared.b16 {%0,%1,%2,%3}, [%4];"
        : "=r"(r[0]), "=r"(r[1]), "=r"(r[2]), "=r"(r[3]) : "r"(a));
}
__device__ __forceinline__ void mma16816(float* d, const uint32_t* A, const uint32_t* b) {
    asm volatile("mma.sync.aligned.m16n8k16.row.col.f32.f16.f16.f32 "
        "{%0,%1,%2,%3},{%4,%5,%6,%7},{%8,%9},{%0,%1,%2,%3};"
        : "+f"(d[0]), "+f"(d[1]), "+f"(d[2]), "+f"(d[3])
        : "r"(A[0]), "r"(A[1]), "r"(A[2]), "r"(A[3]), "r"(b[0]), "r"(b[1]));
}

// ---------------- converters ----------------
__global__ void convert_adj(const float* __restrict__ adj,
                            __half* __restrict__ aH, __half* __restrict__ aL) {
    size_t gid = (size_t)blockIdx.x * 256 + threadIdx.x;
    float4 a = ((const float4*)adj)[gid];
    __half2 h01 = __floats2half2_rn(a.x, a.y);
    __half2 h23 = __floats2half2_rn(a.z, a.w);
    __half2 l01 = __floats2half2_rn(a.x - __low2float(h01), a.y - __high2float(h01));
    __half2 l23 = __floats2half2_rn(a.z - __low2float(h23), a.w - __high2float(h23));
    ((__half2*)aH)[gid * 2]     = h01;
    ((__half2*)aH)[gid * 2 + 1] = h23;
    ((__half2*)aL)[gid * 2]     = l01;
    ((__half2*)aL)[gid * 2 + 1] = l23;
}

// all weights -> scaled fp16 pair, single launch
__global__ void convert_weights(const float* __restrict__ cw1, const float* __restrict__ cw2,
                                const float* __restrict__ m1w, const float* __restrict__ m2w,
                                __half* __restrict__ H, __half* __restrict__ L) {
    int i = blockIdx.x * 256 + threadIdx.x;   // 720896 total
    float x;
    if (i < 131072)      x = cw1[i];
    else if (i < 262144) x = cw2[i - 131072];
    else if (i < 458752) x = m1w[i - 262144];
    else                 x = m2w[i - 458752];
    x *= BSCALE;
    __half h = __float2half_rn(x);
    H[i] = h;
    L[i] = __float2half_rn(x - __half2float(h));
}

__global__ void convert_pair(const float* __restrict__ src,
                             __half* __restrict__ H, __half* __restrict__ L, int n) {
    int i = blockIdx.x * 256 + threadIdx.x;
    if (i < n) {
        float x = src[i] * BSCALE;
        __half h = __float2half_rn(x);
        H[i] = h;
        L[i] = __float2half_rn(x - __half2float(h));
    }
}

__global__ void convert_x(const float* __restrict__ Xl, const float* __restrict__ dis,
                          __half* __restrict__ xlH, __half* __restrict__ xlL,
                          __half* __restrict__ xsH, __half* __restrict__ xsL) {
    int gid = blockIdx.x * 256 + threadIdx.x;
    int r = gid >> 8, c = gid & 255;
    float x = Xl[(size_t)r * LH + c];
    float xl = x * BSCALE;
    float xs = xl * dis[r];
    __half h1 = __float2half_rn(xl);
    __half h2 = __float2half_rn(xs);
    xlH[gid] = h1; xlL[gid] = __float2half_rn(xl - __half2float(h1));
    xsH[gid] = h2; xsL[gid] = __float2half_rn(xs - __half2float(h2));
}

// ---------------- row sums of adj ----------------
__global__ void rowsum_kernel(const float* __restrict__ adj,
                              float* __restrict__ dis, float* __restrict__ rsinv) {
    int gr = blockIdx.x, t = threadIdx.x;
    float4 a4 = ((const float4*)(adj + ((size_t)gr << 10)))[t];
    float s = a4.x + a4.y + a4.z + a4.w;
    s = warpSum(s);
    __shared__ float sm[8];
    if ((t & 31) == 0) sm[t >> 5] = s;
    __syncthreads();
    if (t == 0) {
        float S = sm[0] + sm[1] + sm[2] + sm[3] + sm[4] + sm[5] + sm[6] + sm[7];
        dis[gr]   = rsqrtf(S + 1.0f);
        rsinv[gr] = 1.0f / S;
    }
}

// ---------------- tensor-core adjacency GEMM ----------------
template<int MODE>
__global__ void __launch_bounds__(256, 2)
adjmma(const __half* __restrict__ adjH, const __half* __restrict__ adjL,
       const __half* __restrict__ bH, const __half* __restrict__ bL,
       const float* __restrict__ U32, int ldu,
       const float* __restrict__ aux, int ldaux,
       const float* __restrict__ dis, const float* __restrict__ rsinv,
       float* __restrict__ pout, int ldp,
       __half* __restrict__ poutH, __half* __restrict__ poutL,
       float* __restrict__ hallc) {
    extern __shared__ char smx[];
    const uint32_t sbase = s2u(smx);
    const int t = threadIdx.x;
    const int b = blockIdx.z;
    const int m0 = blockIdx.y << 7;
    const int n0 = blockIdx.x << 7;
    const int w = t >> 5, lane = t & 31;
    const int wm = w >> 1, wn = w & 1;
    const int lr16 = lane & 15, lhi = lane >> 4;

    float acc[2][8][4];
    #pragma unroll
    for (int mi = 0; mi < 2; mi++)
        #pragma unroll
        for (int nj = 0; nj < 8; nj++)
            #pragma unroll
            for (int ci = 0; ci < 4; ci++) acc[mi][nj][ci] = 0.0f;

    const int ar = t >> 2,  asg = t & 3;
    const int bk = t >> 4,  bsg = t & 15;

    auto issue = [&](int kt, int st) {
        uint32_t AHb = sbase + st * 37888;
        uint32_t ALb = AHb + 10240;
        uint32_t BHb = ALb + 10240;
        uint32_t BLb = BHb + 8704;
        #pragma unroll
        for (int it = 0; it < 2; it++) {
            int r = ar + (it << 6);
            size_t gA = ((size_t)b << 20) + ((size_t)(m0 + r) << 10) + (kt << 5) + (asg << 3);
            uint32_t sA = (uint32_t)(r * 80 + (asg << 4));
            cpa16(AHb + sA, adjH + gA);
            cpa16(ALb + sA, adjL + gA);
            int k = bk + (it << 4);
            size_t gB = ((size_t)((b << 10) + (kt << 5) + k) << 8) + n0 + (bsg << 3);
            uint32_t sB = (uint32_t)(k * 272 + (bsg << 4));
            cpa16(BHb + sB, bH + gB);
            cpa16(BLb + sB, bL + gB);
        }
        cpa_commit();
    };

    issue(0, 0);
    for (int kt = 0; kt < 32; kt++) {
        if (kt < 31) { issue(kt + 1, (kt + 1) & 1); cpa_wait<1>(); }
        else         { cpa_wait<0>(); }
        __syncthreads();

        int st = kt & 1;
        uint32_t AHb = sbase + st * 37888;
        uint32_t ALb = AHb + 10240;
        uint32_t BHb = ALb + 10240;
        uint32_t BLb = BHb + 8704;

        #pragma unroll
        for (int kk = 0; kk < 32; kk += 16) {
            uint32_t aHf[2][4], aLf[2][4];
            uint32_t cc2 = (uint32_t)((kk + (lhi << 3)) << 1);
            #pragma unroll
            for (int mi = 0; mi < 2; mi++) {
                uint32_t ro = (uint32_t)((wm * 32 + mi * 16 + lr16) * 80);
                ldmA4(AHb + ro + cc2, aHf[mi]);
                ldmA4(ALb + ro + cc2, aLf[mi]);
            }
            #pragma unroll
            for (int hf = 0; hf < 2; hf++) {
                uint32_t bHf[4][2], bLf[4][2];
                #pragma unroll
                for (int np = 0; np < 2; np++) {
                    uint32_t ko = (uint32_t)((kk + lr16) * 272);
                    uint32_t nc = (uint32_t)((wn * 64 + hf * 32 + np * 16 + (lhi << 3)) << 1);
                    uint32_t r4[4];
                    ldmB4T(BHb + ko + nc, r4);
                    bHf[np*2][0] = r4[0]; bHf[np*2][1] = r4[1];
                    bHf[np*2+1][0] = r4[2]; bHf[np*2+1][1] = r4[3];
                    ldmB4T(BLb + ko + nc, r4);
                    bLf[np*2][0] = r4[0]; bLf[np*2][1] = r4[1];
                    bLf[np*2+1][0] = r4[2]; bLf[np*2+1][1] = r4[3];
                }
                #pragma unroll
                for (int mi = 0; mi < 2; mi++)
                    #pragma unroll
                    for (int nj = 0; nj < 4; nj++) {
                        float* ac = acc[mi][hf * 4 + nj];
                        mma16816(ac, aHf[mi], bHf[nj]);
                        mma16816(ac, aHf[mi], bLf[nj]);
                        mma16816(ac, aLf[mi], bHf[nj]);
                    }
            }
        }
        __syncthreads();
    }

    const int g8 = lane >> 2, t4 = lane & 3;
    #pragma unroll
    for (int mi = 0; mi < 2; mi++)
        #pragma unroll
        for (int nj = 0; nj < 8; nj++)
            #pragma unroll
            for (int ci = 0; ci < 4; ci++) {
                int il = m0 + wm * 32 + mi * 16 + g8 + ((ci >> 1) << 3);
                int cg = n0 + wn * 64 + nj * 8 + (t4 << 1) + (ci & 1);
                int gi = (b << 10) + il;
                float a = acc[mi][nj][ci] * BINV;
                size_t hix = ((size_t)b << 20) + ((size_t)il << 8) + cg;
                if (MODE == 0) {
                    float di = dis[gi];
                    float xv = aux[(size_t)gi * ldaux + cg];
                    hallc[hix] = lky(di * a + di * di * xv);
                } else {
                    float p = 0.5f * (U32[(size_t)gi * ldu + cg] + rsinv[gi] * a);
                    pout[(size_t)gi * ldp + cg] = p;
                    float ps = p * BSCALE;
                    __half ph = __float2half_rn(ps);
                    size_t pix = ((size_t)gi << 8) + cg;
                    poutH[pix] = ph;
                    poutL[pix] = __float2half_rn(ps - __half2float(ph));
                    if (MODE == 1) {
                        float ax = aux[(size_t)gi * ldaux + cg];
                        hallc[hix] = fabsf(ax - p);
                    }
                }
            }
}

// ---------------- dense HMMA GEMM ----------------
template<int EP>
__global__ void __launch_bounds__(256, 2)
hgemm(const __half* __restrict__ AH, const __half* __restrict__ AL, int lda,
      const __half* __restrict__ WH, const __half* __restrict__ WL, int K,
      const float* __restrict__ bias,
      float* __restrict__ out, int ldo,
      __half* __restrict__ poH, __half* __restrict__ poL, int ldp,
      float* __restrict__ zbuf) {
    extern __shared__ char smx[];
    const uint32_t sbase = s2u(smx);
    const int t = threadIdx.x;
    const int m0 = blockIdx.y << 7;
    const int n0 = blockIdx.x << 7;
    const int w = t >> 5, lane = t & 31;
    const int wm = w >> 1, wn = w & 1;
    const int lr16 = lane & 15, lhi = lane >> 4;

    float acc[2][8][4];
    #pragma unroll
    for (int mi = 0; mi < 2; mi++)
        #pragma unroll
        for (int nj = 0; nj < 8; nj++)
            #pragma unroll
            for (int ci = 0; ci < 4; ci++) acc[mi][nj][ci] = 0.0f;

    const int lrow = t >> 1, lsg = t & 1;

    auto issue = [&](int kt, int st) {
        uint32_t AHb = sbase + st * 40960;
        uint32_t ALb = AHb + 10240;
        uint32_t WHb = ALb + 10240;
        uint32_t WLb = WHb + 10240;
        uint32_t so = (uint32_t)(lrow * 80 + (lsg << 5));
        size_t gA = (size_t)(m0 + lrow) * lda + (kt << 5) + (lsg << 4);
        size_t gW = (size_t)(n0 + lrow) * K   + (kt << 5) + (lsg << 4);
        cpa16(AHb + so,      AH + gA);
        cpa16(AHb + so + 16, AH + gA + 8);
        cpa16(ALb + so,      AL + gA);
        cpa16(ALb + so + 16, AL + gA + 8);
        cpa16(WHb + so,      WH + gW);
        cpa16(WHb + so + 16, WH + gW + 8);
        cpa16(WLb + so,      WL + gW);
        cpa16(WLb + so + 16, WL + gW + 8);
        cpa_commit();
    };

    const int nchunks = K >> 5;
    issue(0, 0);
    for (int kt = 0; kt < nchunks; kt++) {
        if (kt < nchunks - 1) { issue(kt + 1, (kt + 1) & 1); cpa_wait<1>(); }
        else                  { cpa_wait<0>(); }
        __syncthreads();

        int st = kt & 1;
        uint32_t AHb = sbase + st * 40960;
        uint32_t ALb = AHb + 10240;
        uint32_t WHb = ALb + 10240;
        uint32_t WLb = WHb + 10240;

        #pragma unroll
        for (int kk = 0; kk < 32; kk += 16) {
            uint32_t aHf[2][4], aLf[2][4];
            uint32_t cc2 = (uint32_t)((kk + (lhi << 3)) << 1);
            #pragma unroll
            for (int mi = 0; mi < 2; mi++) {
                uint32_t ro = (uint32_t)((wm * 32 + mi * 16 + lr16) * 80);
                ldmA4(AHb + ro + cc2, aHf[mi]);
                ldmA4(ALb + ro + cc2, aLf[mi]);
            }
            uint32_t nrow = (uint32_t)(((lane >> 4) << 3) + (lane & 7));
            uint32_t kb   = (uint32_t)(kk * 2 + ((lane >> 3) & 1) * 16);
            #pragma unroll
            for (int hf = 0; hf < 2; hf++) {
                uint32_t bHf[4][2], bLf[4][2];
                #pragma unroll
                for (int np = 0; np < 2; np++) {
                    uint32_t ad = (uint32_t)((wn * 64 + hf * 32 + np * 16 + nrow) * 80) + kb;
                    uint32_t r4[4];
                    ldmA4(WHb + ad, r4);
                    bHf[np*2][0] = r4[0]; bHf[np*2][1] = r4[1];
                    bHf[np*2+1][0] = r4[2]; bHf[np*2+1][1] = r4[3];
                    ldmA4(WLb + ad, r4);
                    bLf[np*2][0] = r4[0]; bLf[np*2][1] = r4[1];
                    bLf[np*2+1][0] = r4[2]; bLf[np*2+1][1] = r4[3];
                }
                #pragma unroll
                for (int mi = 0; mi < 2; mi++)
                    #pragma unroll
                    for (int nj = 0; nj < 4; nj++) {
                        float* ac = acc[mi][hf * 4 + nj];
                        mma16816(ac, aHf[mi], bHf[nj]);
                        mma16816(ac, aHf[mi], bLf[nj]);
                        mma16816(ac, aLf[mi], bHf[nj]);
                    }
            }
        }
        __syncthreads();
    }

    const int g8 = lane >> 2, t4 = lane & 3;
    #pragma unroll
    for (int mi = 0; mi < 2; mi++)
        #pragma unroll
        for (int nj = 0; nj < 8; nj++)
            #pragma unroll
            for (int ci = 0; ci < 4; ci++) {
                int rg = m0 + wm * 32 + mi * 16 + g8 + ((ci >> 1) << 3);
                int cg = n0 + wn * 64 + nj * 8 + (t4 << 1) + (ci & 1);
                float v = acc[mi][nj][ci] * ACCINV + __ldg(&bias[cg]);
                if (EP == 1) {
                    float o = lky(v);
                    if (out) out[(size_t)rg * ldo + cg] = o;
                    if (poH) {
                        float ps = o * BSCALE;
                        __half ph = __float2half_rn(ps);
                        size_t pix = (size_t)rg * ldp + cg;
                        poH[pix] = ph;
                        poL[pix] = __float2half_rn(ps - __half2float(ph));
                    }
                } else {
                    uint32_t idx = ((uint32_t)rg << 10) + (uint32_t)cg;
                    float z = (tanhf(v) * 40.0f + gumbel_noise(idx)) * 10.0f;
                    zbuf[idx] = z;
                }
            }
}

// ---------------- dense GEMM (FFMA, only w_in) ----------------
__global__ void __launch_bounds__(256)
dense_gemm(const float* __restrict__ X, int ldx,
           const float* __restrict__ W, int K,
           const float* __restrict__ bias,
           float* __restrict__ out, int ldo) {
    __shared__ float As[16][132];
    __shared__ float Bs[16][132];
    const int t  = threadIdx.x;
    const int m0 = blockIdx.y << 7;
    const int n0 = blockIdx.x << 7;
    const int tx = t & 15, ty = t >> 4;
    const int lr = t >> 1;
    const int lk = (t & 1) << 3;

    float acc[8][8];
    #pragma unroll
    for (int i = 0; i < 8; i++)
        #pragma unroll
        for (int j = 0; j < 8; j++) acc[i][j] = 0.0f;

    const float* Ap = X + (size_t)(m0 + lr) * ldx + lk;
    const float* Bp = W + (size_t)(n0 + lr) * K + lk;

    for (int kt = 0; kt < K; kt += 16) {
        float4 av0 = *(const float4*)(Ap + kt);
        float4 av1 = *(const float4*)(Ap + kt + 4);
        float4 bv0 = *(const float4*)(Bp + kt);
        float4 bv1 = *(const float4*)(Bp + kt + 4);
        As[lk+0][lr]=av0.x; As[lk+1][lr]=av0.y; As[lk+2][lr]=av0.z; As[lk+3][lr]=av0.w;
        As[lk+4][lr]=av1.x; As[lk+5][lr]=av1.y; As[lk+6][lr]=av1.z; As[lk+7][lr]=av1.w;
        Bs[lk+0][lr]=bv0.x; Bs[lk+1][lr]=bv0.y; Bs[lk+2][lr]=bv0.z; Bs[lk+3][lr]=bv0.w;
        Bs[lk+4][lr]=bv1.x; Bs[lk+5][lr]=bv1.y; Bs[lk+6][lr]=bv1.z; Bs[lk+7][lr]=bv1.w;
        __syncthreads();
        #pragma unroll
        for (int k = 0; k < 16; k++) {
            float af[8], bf[8];
            *(float4*)(af)     = *(const float4*)&As[k][(ty<<3)];
            *(float4*)(af + 4) = *(const float4*)&As[k][(ty<<3) + 4];
            *(float4*)(bf)     = *(const float4*)&Bs[k][(tx<<3)];
            *(float4*)(bf + 4) = *(const float4*)&Bs[k][(tx<<3) + 4];
            #pragma unroll
            for (int i = 0; i < 8; i++)
                #pragma unroll
                for (int j = 0; j < 8; j++)
                    acc[i][j] = fmaf(af[i], bf[j], acc[i][j]);
        }
        __syncthreads();
    }

    #pragma unroll
    for (int i = 0; i < 8; i++) {
        int rg = m0 + (ty << 3) + i;
        #pragma unroll
        for (int j = 0; j < 8; j++) {
            int cg = n0 + (tx << 3) + j;
            out[(size_t)rg * ldo + cg] = acc[i][j] + __ldg(&bias[cg]);
        }
    }
}

// ---------------- attention + channel mix -> hp fp16 pair ----------------
__global__ void attention_kernel(const float* __restrict__ Xl, int ldx,
                                 const float* __restrict__ hall,
                                 const float* __restrict__ a,
                                 __half* __restrict__ hpH, __half* __restrict__ hpL) {
    int n = blockIdx.x, b = blockIdx.y, t = threadIdx.x;
    float xv = Xl[(size_t)((b << 10) + n) * ldx + t];
    float hv[4];
    size_t hbase = ((size_t)b << 20) + ((size_t)n << 8) + t;
    #pragma unroll
    for (int c = 0; c < 4; c++) hv[c] = hall[hbase + ((size_t)c << 18)];
    float a1 = a[t], a2 = a[256 + t];
    float p[5];
    p[0] = fmaxf(xv, 0.0f) * a1;
    #pragma unroll
    for (int c = 0; c < 4; c++) p[1 + c] = fmaxf(hv[c], 0.0f) * a2;

    __shared__ float sm[5][8];
    #pragma unroll
    for (int q = 0; q < 5; q++) {
        float s = warpSum(p[q]);
        if ((t & 31) == 0) sm[q][t >> 5] = s;
    }
    __syncthreads();
    float S[5];
    #pragma unroll
    for (int q = 0; q < 5; q++) {
        float s = sm[q][0];
        #pragma unroll
        for (int w = 1; w < 8; w++) s += sm[q][w];
        S[q] = s;
    }
    float e0 = S[0] + S[1], e1 = S[0] + S[2], e2 = S[0] + S[3], e3 = S[0] + S[4];
    float M = fmaxf(fmaxf(e0, e1), fmaxf(e2, e3));
    float w0 = __expf(e0 - M), w1 = __expf(e1 - M), w2 = __expf(e2 - M), w3 = __expf(e3 - M);
    float ws = w0 + w1 + w2 + w3;
    float o = w0 * hv[0] + w1 * hv[1] + w2 * hv[2] + w3 * hv[3];
    float hpv = 0.25f * o / ws;
    float ps = hpv * BSCALE;
    __half ph = __float2half_rn(ps);
    size_t pix = (size_t)((b << 10) + n) * HH + t;
    hpH[pix] = ph;
    hpL[pix] = __float2half_rn(ps - __half2float(ph));
}

// ---------------- persistent sinkhorn (iterations + final normalize) ----------------
// grid = NBLK (=256) blocks; block bid: batch = bid>>4, chunk = bid&15 (64 rows / 64 cols)
__global__ void __launch_bounds__(256)
sinkhorn_all(const float* __restrict__ Z0, float* __restrict__ P,
             float* __restrict__ u, float* __restrict__ v,
             float* __restrict__ r, float* __restrict__ c) {
    const int t = threadIdx.x;
    const int bid = blockIdx.x;
    const int b = bid >> 4, ch = bid & 15;
    const int lane = t & 31, w = t >> 5;
    __shared__ float vec[1024];
    __shared__ float red[256];
    __shared__ float red2[256];
    unsigned gen = *(volatile unsigned*)&g_bargen;

    // init u,v slice
    if (t < 64) {
        u[(b << 10) + (ch << 6) + t] = 0.0f;
        v[(b << 10) + (ch << 6) + t] = 0.0f;
    }
    gridbar(gen);

    const float* zb = Z0 + ((size_t)b << 20);

    for (int it = 0; it < 20; it++) {
        // ---- row phase: u = LSE_cols(Z0 - v) ----
        for (int i = t; i < 1024; i += 256) vec[i] = v[(b << 10) + i];
        __syncthreads();
        #pragma unroll 1
        for (int rr = 0; rr < 8; rr++) {
            int row = (ch << 6) + (w << 3) + rr;
            const float* zr = zb + ((size_t)row << 10);
            float a[32];
            float m = -INFINITY;
            #pragma unroll
            for (int q = 0; q < 8; q++) {
                int idx = lane + (q << 5);
                float4 z4 = ((const float4*)zr)[idx];
                int cb = idx << 2;
                a[q*4+0] = z4.x - vec[cb];
                a[q*4+1] = z4.y - vec[cb+1];
                a[q*4+2] = z4.z - vec[cb+2];
                a[q*4+3] = z4.w - vec[cb+3];
                m = fmaxf(m, fmaxf(fmaxf(a[q*4], a[q*4+1]), fmaxf(a[q*4+2], a[q*4+3])));
            }
            m = warpMax(m);
            float s = 0.0f;
            #pragma unroll
            for (int q = 0; q < 32; q++) s += __expf(a[q] - m);
            s = warpSum(s);
            if (lane == 0) u[(b << 10) + row] = m + __logf(s);
        }
        gridbar(gen);

        // ---- col phase: v = LSE_rows(Z0 - u), online ----
        for (int i = t; i < 1024; i += 256) vec[i] = u[(b << 10) + i];
        __syncthreads();
        {
            int jj = t & 63, seg = t >> 6;
            int j = (ch << 6) + jj;
            float m = -INFINITY, s = 0.0f;
            int i0 = seg << 8;
            for (int i = i0; i < i0 + 256; i++) {
                float a = zb[((size_t)i << 10) + j] - vec[i];
                if (a > m) { s = s * __expf(m - a) + 1.0f; m = a; }
                else       { s += __expf(a - m); }
            }
            red[t] = m; red2[t] = s;
            __syncthreads();
            if (seg == 0) {
                float m0 = red[jj], m1 = red[jj+64], m2 = red[jj+128], m3 = red[jj+192];
                float M = fmaxf(fmaxf(m0, m1), fmaxf(m2, m3));
                float S = red2[jj]     * __expf(m0 - M) + red2[jj+64]  * __expf(m1 - M)
                        + red2[jj+128] * __expf(m2 - M) + red2[jj+192] * __expf(m3 - M);
                v[(b << 10) + j] = M + __logf(S);
            }
        }
        gridbar(gen);
    }

    // ---- P = exp(Z0-u-v), r = rowsum ----
    for (int i = t; i < 1024; i += 256) vec[i] = v[(b << 10) + i];
    __syncthreads();
    float* pb = P + ((size_t)b << 20);
    #pragma unroll 1
    for (int rr = 0; rr < 8; rr++) {
        int row = (ch << 6) + (w << 3) + rr;
        float uu = u[(b << 10) + row];
        const float* zr = zb + ((size_t)row << 10);
        float* pr = pb + ((size_t)row << 10);
        float s = 0.0f;
        #pragma unroll
        for (int q = 0; q < 8; q++) {
            int idx = lane + (q << 5);
            float4 z4 = ((const float4*)zr)[idx];
            int cb = idx << 2;
            float4 e;
            e.x = __expf(z4.x - uu - vec[cb]);
            e.y = __expf(z4.y - uu - vec[cb+1]);
            e.z = __expf(z4.z - uu - vec[cb+2]);
            e.w = __expf(z4.w - uu - vec[cb+3]);
            ((float4*)pr)[idx] = e;
            s += e.x + e.y + e.z + e.w;
        }
        s = warpSum(s);
        if (lane == 0) r[(b << 10) + row] = s;
    }
    gridbar(gen);

    // ---- c_j = sum_i P[i,j]/r_i ----
    for (int i = t; i < 1024; i += 256) vec[i] = 1.0f / r[(b << 10) + i];
    __syncthreads();
    {
        int jj = t & 63, seg = t >> 6;
        int j = (ch << 6) + jj;
        float s = 0.0f;
        int i0 = seg << 8;
        for (int i = i0; i < i0 + 256; i++)
            s += pb[((size_t)i << 10) + j] * vec[i];
        red[t] = s;
        __syncthreads();
        if (seg == 0)
            c[(b << 10) + j] = red[jj] + red[jj+64] + red[jj+128] + red[jj+192];
    }
    gridbar(gen);

    // ---- final scale: P = P / r_i / c_j ----
    for (int i = t; i < 1024; i += 256) vec[i] = c[(b << 10) + i];
    __syncthreads();
    #pragma unroll 1
    for (int rr = 0; rr < 8; rr++) {
        int row = (ch << 6) + (w << 3) + rr;
        float rin = 1.0f / r[(b << 10) + row];
        float* pr = pb + ((size_t)row << 10);
        #pragma unroll
        for (int q = 0; q < 8; q++) {
            int idx = lane + (q << 5);
            float4 p4 = ((float4*)pr)[idx];
            int cb = idx << 2;
            p4.x = p4.x * rin / vec[cb];
            p4.y = p4.y * rin / vec[cb+1];
            p4.z = p4.z * rin / vec[cb+2];
            p4.w = p4.w * rin / vec[cb+3];
            ((float4*)pr)[idx] = p4;
        }
    }
}

// ---------------- launch ----------------
extern "C" void kernel_launch(void* const* d_in, const int* in_sizes, int n_in,
                              void* d_out, int out_size) {
    (void)in_sizes; (void)n_in; (void)out_size;
    const float* X    = (const float*)d_in[0];
    const float* adj  = (const float*)d_in[1];
    const float* w_in = (const float*)d_in[2];
    const float* b_in = (const float*)d_in[3];
    const float* cw1  = (const float*)d_in[4];
    const float* cb1  = (const float*)d_in[5];
    const float* cw2  = (const float*)d_in[6];
    const float* cb2  = (const float*)d_in[7];
    const float* ca   = (const float*)d_in[8];
    const float* m1w  = (const float*)d_in[9];
    const float* m1b  = (const float*)d_in[10];
    const float* m2w  = (const float*)d_in[11];
    const float* m2b  = (const float*)d_in[12];

    float* outP = (float*)d_out;
    float* Z0   = outP + (size_t)NB * NN * NN;

    float *hall, *hcat, *t0, *t1, *t2, *dis, *rsinv, *u, *v, *r, *c;
    __half *adjH, *adjL, *xlH, *xlL, *xsH, *xsL, *p0H, *p0L, *p1H, *p1L, *p2H, *p2L;
    __half *wH, *wL, *hpH, *hpL, *htH, *htL, *m1H, *m1L, *hcH, *hcL;
    cudaGetSymbolAddress((void**)&hall, g_hall);
    cudaGetSymbolAddress((void**)&hcat, g_hcat);
    cudaGetSymbolAddress((void**)&t0, g_t0);
    cudaGetSymbolAddress((void**)&t1, g_t1);
    cudaGetSymbolAddress((void**)&t2, g_t2);
    cudaGetSymbolAddress((void**)&dis, g_dis);
    cudaGetSymbolAddress((void**)&rsinv, g_rsinv);
    cudaGetSymbolAddress((void**)&u, g_u);
    cudaGetSymbolAddress((void**)&v, g_v);
    cudaGetSymbolAddress((void**)&r, g_r);
    cudaGetSymbolAddress((void**)&c, g_c);
    cudaGetSymbolAddress((void**)&adjH, g_adjH);
    cudaGetSymbolAddress((void**)&adjL, g_adjL);
    cudaGetSymbolAddress((void**)&xlH, g_xlH);
    cudaGetSymbolAddress((void**)&xlL, g_xlL);
    cudaGetSymbolAddress((void**)&xsH, g_xsH);
    cudaGetSymbolAddress((void**)&xsL, g_xsL);
    cudaGetSymbolAddress((void**)&p0H, g_p0H);
    cudaGetSymbolAddress((void**)&p0L, g_p0L);
    cudaGetSymbolAddress((void**)&p1H, g_p1H);
    cudaGetSymbolAddress((void**)&p1L, g_p1L);
    cudaGetSymbolAddress((void**)&p2H, g_p2H);
    cudaGetSymbolAddress((void**)&p2L, g_p2L);
    cudaGetSymbolAddress((void**)&wH, g_wH);
    cudaGetSymbolAddress((void**)&wL, g_wL);
    cudaGetSymbolAddress((void**)&hpH, g_hpH);
    cudaGetSymbolAddress((void**)&hpL, g_hpL);
    cudaGetSymbolAddress((void**)&htH, g_htH);
    cudaGetSymbolAddress((void**)&htL, g_htL);
    cudaGetSymbolAddress((void**)&m1H, g_m1H);
    cudaGetSymbolAddress((void**)&m1L, g_m1L);
    cudaGetSymbolAddress((void**)&hcH, g_hcH);
    cudaGetSymbolAddress((void**)&hcL, g_hcL);

    const int SMEM_A = 75776;
    const int SMEM_H = 81920;
    cudaFuncSetAttribute(adjmma<0>, cudaFuncAttributeMaxDynamicSharedMemorySize, SMEM_A);
    cudaFuncSetAttribute(adjmma<1>, cudaFuncAttributeMaxDynamicSharedMemorySize, SMEM_A);
    cudaFuncSetAttribute(adjmma<2>, cudaFuncAttributeMaxDynamicSharedMemorySize, SMEM_A);
    cudaFuncSetAttribute(hgemm<1>, cudaFuncAttributeMaxDynamicSharedMemorySize, SMEM_H);
    cudaFuncSetAttribute(hgemm<2>, cudaFuncAttributeMaxDynamicSharedMemorySize, SMEM_H);

    const size_t CH = (size_t)NN * HH;

    rowsum_kernel<<<NB * NN, 256>>>(adj, dis, rsinv);
    convert_adj<<<16384, 256>>>(adj, adjH, adjL);
    convert_weights<<<2816, 256>>>(cw1, cw2, m1w, m2w, wH, wL);

    dense_gemm<<<dim3(2, 128), 256>>>(X, 128, w_in, 128, b_in, hcat, LH);

    for (int l = 0; l < 2; l++) {
        const float* Xl = hcat + l * HH;
        convert_x<<<16384, 256>>>(Xl, dis, xlH, xlL, xsH, xsL);
        dim3 ag(2, 8, NB);
        adjmma<0><<<ag, 256, SMEM_A>>>(adjH, adjL, xsH, xsL, nullptr, 0, Xl, LH,
                                       dis, rsinv, nullptr, 0, nullptr, nullptr, hall + 0 * CH);
        adjmma<1><<<ag, 256, SMEM_A>>>(adjH, adjL, xlH, xlL, Xl, LH, Xl, LH,
                                       dis, rsinv, t0, HH, p0H, p0L, hall + 1 * CH);
        adjmma<1><<<ag, 256, SMEM_A>>>(adjH, adjL, p0H, p0L, t0, HH, t0, HH,
                                       dis, rsinv, t1, HH, p1H, p1L, hall + 2 * CH);
        adjmma<2><<<ag, 256, SMEM_A>>>(adjH, adjL, p1H, p1L, t1, HH, nullptr, 0,
                                       dis, rsinv, t2, HH, p2H, p2L, nullptr);
        adjmma<1><<<ag, 256, SMEM_A>>>(adjH, adjL, p2H, p2L, t2, HH, t1, HH,
                                       dis, rsinv, t0, HH, p0H, p0L, hall + 3 * CH);

        attention_kernel<<<dim3(NN, NB), 256>>>(Xl, LH, hall, ca + l * 2 * HH, hpH, hpL);

        hgemm<1><<<dim3(2, 128), 256, SMEM_H>>>(hpH, hpL, HH,
            wH + OW_CW1 + l * 65536, wL + OW_CW1 + l * 65536, HH, cb1 + l * HH,
            nullptr, 0, htH, htL, HH, nullptr);
        hgemm<1><<<dim3(2, 128), 256, SMEM_H>>>(htH, htL, HH,
            wH + OW_CW2 + l * 65536, wL + OW_CW2 + l * 65536, HH, cb2 + l * HH,
            hcat + (l + 1) * HH, LH, nullptr, nullptr, 0, nullptr);
    }

    convert_pair<<<49152, 256>>>(hcat, hcH, hcL, 16384 * LH);
    hgemm<1><<<dim3(2, 128), 256, SMEM_H>>>(hcH, hcL, LH,
        wH + OW_M1W, wL + OW_M1W, LH, m1b,
        nullptr, 0, m1H, m1L, HH, nullptr);
    hgemm<2><<<dim3(8, 128), 256, SMEM_H>>>(m1H, m1L, HH,
        wH + OW_M2W, wL + OW_M2W, HH, m2b,
        nullptr, 0, nullptr, nullptr, 0, Z0);

    // sinkhorn: persistent kernel (iterations + final normalization)
    sinkhorn_all<<<NBLK, 256>>>(Z0, outP, u, v, r, c);
}